// round 14
// baseline (speedup 1.0000x reference)
#include <cuda_runtime.h>
#include <cuda_fp16.h>
#include <math.h>
#include <stdint.h>

#define NPTS 65536
#define KNN  16
#define DCH  96
#define HCH  384
#define HD   256

// ---------------- scratch (allocation-free: device globals) ----------------
__device__ float    g_f[(size_t)NPTS * DCH];     // running feature fp32 [N,96]
__device__ uint32_t g_f2[(size_t)NPTS * 48];     // fp16x2 shadow of f
__device__ uint32_t g_y2[(size_t)NPTS * 48];     // LFP projection, fp16x2 [N,96]
__device__ float    g_hb[HD];                    // head bias row

// pre-converted weights: [Nc][K] fp16 (B^T layout, n-major rows)
// LFP 4x(96x96) | UP 3x(384x96) | DOWN 3x(96x384) | HEAD (256x96, pp_g folded) | NE3 (96x32)
#define WOFF_LFP   0
#define WOFF_UP    36864
#define WOFF_DOWN  147456
#define WOFF_HEAD  258048
#define WOFF_NE    282624
#define WTOTAL     285696
__device__ __half g_wh[WTOTAL];

// exact erf for host-invisible precompute paths
__device__ __forceinline__ float gelu_exact(float v) {
    return 0.5f * v * (1.0f + erff(v * 0.70710678118654752440f));
}

// fast gelu: Abramowitz-Stegun 7.1.26 erf (|abs err| <= 1.5e-7) + __expf
__device__ __forceinline__ float gelu_fast(float v) {
    const float x = v * 0.70710678118654752440f;
    const float ax = fabsf(x);
    const float t = 1.0f / fmaf(0.3275911f, ax, 1.0f);
    float y = fmaf(t, 1.061405429f, -1.453152027f);
    y = fmaf(t, y, 1.421413741f);
    y = fmaf(t, y, -0.284496736f);
    y = fmaf(t, y, 0.254829592f);
    y *= t;
    const float e = __expf(-x * x);
    float er = fmaf(-y, e, 1.0f);
    er = copysignf(er, x);
    return 0.5f * v * (1.0f + er);
}

__device__ __forceinline__ uint32_t smem_u32(const void* p) {
    uint32_t a;
    asm("{ .reg .u64 t; cvta.to.shared.u64 t, %1; cvt.u32.u64 %0, t; }" : "=r"(a) : "l"(p));
    return a;
}

__device__ __forceinline__ uint32_t pk2h(float x, float y) {
    __half2 h = __floats2half2_rn(x, y);
    return *(uint32_t*)&h;
}

__device__ __forceinline__ void mma16816(float* d, const uint32_t* a, const uint32_t* b) {
    asm volatile(
        "mma.sync.aligned.m16n8k16.row.col.f32.f16.f16.f32 "
        "{%0,%1,%2,%3}, {%4,%5,%6,%7}, {%8,%9}, {%0,%1,%2,%3};"
        : "+f"(d[0]), "+f"(d[1]), "+f"(d[2]), "+f"(d[3])
        : "r"(a[0]), "r"(a[1]), "r"(a[2]), "r"(a[3]), "r"(b[0]), "r"(b[1]));
}

__device__ __forceinline__ void ldm_x4(uint32_t* r, uint32_t addr) {
    asm volatile("ldmatrix.sync.aligned.m8n8.x4.shared.b16 {%0,%1,%2,%3}, [%4];"
        : "=r"(r[0]), "=r"(r[1]), "=r"(r[2]), "=r"(r[3]) : "r"(addr));
}

__device__ __forceinline__ void cp16(uint32_t saddr, const void* gaddr) {
    asm volatile("cp.async.ca.shared.global [%0], [%1], 16;" :: "r"(saddr), "l"(gaddr));
}
#define CP_COMMIT() asm volatile("cp.async.commit_group;" ::: "memory")
template <int N> __device__ __forceinline__ void cp_wait() {
    asm volatile("cp.async.wait_group %0;" :: "n"(N) : "memory");
}

// float max over an arbitrary lane mask via redux.sync.max.s32 (order-preserving flip)
__device__ __forceinline__ float redux_maxf(float v, uint32_t mask) {
    int u = __float_as_int(v);
    u ^= (u >> 31) & 0x7fffffff;
    int r;
    asm volatile("redux.sync.max.s32 %0, %1, %2;" : "=r"(r) : "r"(u), "r"(mask));
    r ^= (r >> 31) & 0x7fffffff;
    return __int_as_float(r);
}

// =============== weight pre-conversion: fp32 [K][Nc] -> fp16 [Nc][K] ===============
__global__ void conv_weights(const float* __restrict__ lfp_w,
                             const float* __restrict__ m0_w1, const float* __restrict__ ms_w1,
                             const float* __restrict__ m0_w2, const float* __restrict__ ms_w2,
                             const float* __restrict__ pp_w,  const float* __restrict__ pp_g,
                             const float* __restrict__ ne_w3)
{
    int idx = blockIdx.x * blockDim.x + threadIdx.x;
    if (idx >= WTOTAL) return;
    float v;
    if (idx < WOFF_UP) {                       // LFP: 4 x [96n][96k]
        int i = idx / 9216, r = idx % 9216, n = r / 96, k = r % 96;
        v = lfp_w[i * 9216 + k * 96 + n];
    } else if (idx < WOFF_DOWN) {              // UP: 3 x [384n][96k], src [96][384]
        int t = idx - WOFF_UP, j = t / 36864, r = t % 36864, n = r / 96, k = r % 96;
        const float* src = (j == 0) ? m0_w1 : (ms_w1 + (size_t)(j - 1) * 96 * 384);
        v = src[k * 384 + n];
    } else if (idx < WOFF_HEAD) {              // DOWN: 3 x [96n][384k], src [384][96]
        int t = idx - WOFF_DOWN, j = t / 36864, r = t % 36864, n = r / 384, k = r % 384;
        const float* src = (j == 0) ? m0_w2 : (ms_w2 + (size_t)(j - 1) * 384 * 96);
        v = src[k * 96 + n];
    } else if (idx < WOFF_NE) {                // HEAD: [256n][96k], pp_g folded in
        int t = idx - WOFF_HEAD, n = t / 96, k = t % 96;
        v = pp_w[k * 256 + n] * pp_g[k];
    } else {                                   // NE3: [96n][32k], src [32][96]
        int t = idx - WOFF_NE, n = t / 32, k = t % 32;
        v = ne_w3[k * 96 + n];
    }
    g_wh[idx] = __float2half_rn(v);
}

// head bias row: hb[n] = sum_k pp_b[k] * pp_w[k][n]
__global__ void head_bias(const float* __restrict__ pp_b, const float* __restrict__ pp_w,
                          float* __restrict__ hb)
{
    const int n = blockIdx.x * blockDim.x + threadIdx.x;
    if (n >= HD) return;
    float s = 0.f;
#pragma unroll
    for (int k = 0; k < DCH; k++) s += pp_b[k] * pp_w[k * HD + n];
    hb[n] = s;
}

#define AS   20                    // smem row stride in u32 per 32-k chunk
#define CHP  (128 * AS)            // u32 per chunk-plane for A/H (2560)
#define WCHP (96 * AS)             // u32 per chunk-plane for W  (1920)

// =============== fused MLP: f += bn(gelu(f@W1 + b1) @ W2) ===============
// CTA = 128 points, 256 threads = 8 warps (2M x 4N), warp tile 64 x 24.  (R12 structure)
#define OFF_H  (3 * CHP)                      // 7680
#define OFF_W1 (OFF_H + 3 * CHP)              // 15360
#define OFF_W2 (OFF_W1 + 3 * WCHP)            // 21120
#define FUSED_SMEM ((OFF_W2 + 3 * WCHP) * 4)  // 107520 B

__global__ void __launch_bounds__(256, 2) fused_mlp(
    const uint32_t* __restrict__ F2,   // fp16 shadow [N][48]
    const __half* __restrict__ W1, const __half* __restrict__ W2,  // [384][96], [96][384]
    const float* __restrict__ b1,
    const float* __restrict__ bng, const float* __restrict__ bnb,
    float* __restrict__ Fout, uint32_t* __restrict__ F2out)
{
    extern __shared__ uint32_t sm[];
    const uint32_t sb = smem_u32(sm);

    const int tid = threadIdx.x, wid = tid >> 5, lane = tid & 31;
    const int g = lane >> 2, t = lane & 3;
    const int warp_m = wid >> 2, warp_n = wid & 3;
    const int m0 = blockIdx.x * 128;

    const uint32_t aoff = ((warp_m * 64 + (lane & 7) + ((lane >> 3) & 1) * 8) * AS + (lane >> 4) * 4) * 4;
    const uint32_t boff = ((warp_n * 24 + (lane & 7)) * AS + (lane >> 3) * 4) * 4;

    // ---- f tile [128 x 96] fp16 shadow -> chunked smem via cp.async ----
#pragma unroll
    for (int e = tid; e < 128 * 12; e += 256) {
        const int row = e / 12, qu = e % 12;
        const int chunk = qu >> 2, q4 = (qu & 3) * 4;
        cp16(sb + (chunk * CHP + row * AS + q4) * 4,
             &F2[(size_t)(m0 + row) * 48 + chunk * 16 + q4]);
    }

    float out[4][3][4] = {};

    auto stage_w = [&](int s) {
#pragma unroll
        for (int e = tid; e < 96 * 12; e += 256) {
            const int row = e / 12, qu = e % 12;
            const int chunk = qu >> 2, q4 = (qu & 3) * 4;
            cp16(sb + (OFF_W1 + chunk * WCHP + row * AS + q4) * 4,
                 &W1[(size_t)(s * 96 + row) * 96 + qu * 8]);
            cp16(sb + (OFF_W2 + chunk * WCHP + row * AS + q4) * 4,
                 &W2[(size_t)row * 384 + s * 96 + qu * 8]);
        }
    };

    auto gemm_chunk = [&](uint32_t aB, uint32_t wB, float acc[4][3][4]) {
        uint32_t bh[3][4];
#pragma unroll
        for (int j = 0; j < 3; j++)
            ldm_x4(bh[j], wB + boff + j * 8 * AS * 4);
#pragma unroll
        for (int ks = 0; ks < 2; ks++) {
#pragma unroll
            for (int i = 0; i < 4; i++) {
                uint32_t ah[4];
                ldm_x4(ah, aB + aoff + (i * 16 * AS + ks * 8) * 4);
#pragma unroll
                for (int j = 0; j < 3; j++)
                    mma16816(acc[i][j], ah, &bh[j][ks * 2]);
            }
        }
    };

    for (int s = 0; s < 4; s++) {
        stage_w(s);
        CP_COMMIT();
        cp_wait<0>();      // f tile (s==0) + W slice complete
        __syncthreads();

        // ---- GEMM1: hid = f @ W1[s] ----
        float hid[4][3][4] = {};
#pragma unroll
        for (int kc = 0; kc < 3; kc++)
            gemm_chunk(sb + kc * CHP * 4, sb + (OFF_W1 + kc * WCHP) * 4, hid);

        // ---- bias + fast gelu -> fp16 H tile ----
#pragma unroll
        for (int i = 0; i < 4; i++) {
            const int rm = warp_m * 64 + i * 16 + g;
#pragma unroll
            for (int j = 0; j < 3; j++) {
                const int nn = warp_n * 24 + j * 8 + t * 2;
                const float b0 = b1[s * 96 + nn], b1v = b1[s * 96 + nn + 1];
                const uint32_t h01 = pk2h(gelu_fast(hid[i][j][0] + b0), gelu_fast(hid[i][j][1] + b1v));
                const uint32_t h23 = pk2h(gelu_fast(hid[i][j][2] + b0), gelu_fast(hid[i][j][3] + b1v));
                const int chunk = nn >> 5, q2 = (nn & 31) >> 1;
                uint32_t* p = sm + OFF_H + chunk * CHP;
                p[rm * AS + q2]       = h01;
                p[(rm + 8) * AS + q2] = h23;
            }
        }
        __syncthreads();

        // ---- GEMM2 partial: out += H @ W2[:, s*96:(s+1)*96] ----
#pragma unroll
        for (int kc = 0; kc < 3; kc++)
            gemm_chunk(sb + (OFF_H + kc * CHP) * 4, sb + (OFF_W2 + kc * WCHP) * 4, out);

        __syncthreads();
    }

    // ---- epilogue: f += out * bng + bnb ; update fp16 shadow ----
#pragma unroll
    for (int i = 0; i < 4; i++) {
        const int rm = m0 + warp_m * 64 + i * 16 + g;
#pragma unroll
        for (int j = 0; j < 3; j++) {
            const int n = warp_n * 24 + j * 8 + t * 2;
            const float s0 = bng[n], s1 = bng[n + 1];
            const float q0 = bnb[n], q1 = bnb[n + 1];
            float* p0 = &Fout[(size_t)rm * 96 + n];
            float* p1 = &Fout[(size_t)(rm + 8) * 96 + n];
            float2 c0 = *(float2*)p0;
            float2 c1 = *(float2*)p1;
            const float a0 = c0.x + out[i][j][0] * s0 + q0;
            const float a1 = c0.y + out[i][j][1] * s1 + q1;
            const float a2 = c1.x + out[i][j][2] * s0 + q0;
            const float a3 = c1.y + out[i][j][3] * s1 + q1;
            *(float2*)p0 = make_float2(a0, a1);
            *(float2*)p1 = make_float2(a2, a3);
            F2out[(size_t)rm * 48 + n / 2]       = pk2h(a0, a1);
            F2out[(size_t)(rm + 8) * 48 + n / 2] = pk2h(a2, a3);
        }
    }
}

// =============== HMMA GEMM (standalone: LFP proj + head) ===============
// A from fp16 shadow via cp.async. All K=96 chunks loaded up-front (3 commit groups).
template <int NT, bool OUT16, bool BIAS>
__global__ void __launch_bounds__(256, 2) hmma_gemm(
    const uint32_t* __restrict__ A2,   // fp16 shadow [M][48]
    const __half* __restrict__ W,      // [Nc][96]
    void* __restrict__ Cv,
    const float* __restrict__ bias,
    int Nc)
{
    constexpr int KTOT = 96;
    constexpr int WN   = NT / 4;
    constexpr int NTL  = WN / 8;
    constexpr int ASZ  = 128 * AS;
    constexpr int BSZ  = NT * AS;
    constexpr int BUFU = ASZ + BSZ;

    extern __shared__ uint32_t sm[];
    const uint32_t sb = smem_u32(sm);

    const int tid = threadIdx.x, wid = tid >> 5, lane = tid & 31;
    const int g = lane >> 2, t = lane & 3;
    const int warp_m = wid >> 2, warp_n = wid & 3;
    const int m0 = blockIdx.y * 128, n0 = blockIdx.x * NT;

    float acc[4][NTL][4] = {};

    const uint32_t aoff = ((warp_m * 64 + (lane & 7) + ((lane >> 3) & 1) * 8) * AS + (lane >> 4) * 4) * 4;
    const uint32_t boff = ((warp_n * WN + (lane & 7)) * AS + (lane >> 3) * 4) * 4;

#pragma unroll
    for (int kc = 0; kc < 3; kc++) {
        const uint32_t base = sb + kc * BUFU * 4;
#pragma unroll
        for (int e = tid; e < 128 * 4; e += 256) {
            const int row = e >> 2, q4 = (e & 3) * 4;
            cp16(base + (row * AS + q4) * 4,
                 &A2[(size_t)(m0 + row) * 48 + kc * 16 + q4]);
        }
#pragma unroll
        for (int e = tid; e < NT * 4; e += 256) {
            const int row = e >> 2, q = e & 3;
            cp16(base + (ASZ + row * AS + q * 4) * 4,
                 &W[(size_t)(n0 + row) * KTOT + kc * 32 + q * 8]);
        }
        CP_COMMIT();
    }

    auto compute = [&](uint32_t bufbase) {
        const uint32_t ahB = bufbase + aoff;
        const uint32_t bhB = bufbase + ASZ * 4 + boff;
        uint32_t bh[NTL][4];
#pragma unroll
        for (int j = 0; j < NTL; j++)
            ldm_x4(bh[j], bhB + j * 8 * AS * 4);
#pragma unroll
        for (int ks = 0; ks < 2; ks++) {
#pragma unroll
            for (int i = 0; i < 4; i++) {
                uint32_t ah[4];
                ldm_x4(ah, ahB + (i * 16 * AS + ks * 8) * 4);
#pragma unroll
                for (int j = 0; j < NTL; j++)
                    mma16816(acc[i][j], ah, &bh[j][ks * 2]);
            }
        }
    };

    cp_wait<2>(); __syncthreads(); compute(sb);
    cp_wait<1>(); __syncthreads(); compute(sb + BUFU * 4);
    cp_wait<0>(); __syncthreads(); compute(sb + 2 * BUFU * 4);

#pragma unroll
    for (int i = 0; i < 4; i++) {
        const int rm = m0 + warp_m * 64 + i * 16 + g;
#pragma unroll
        for (int j = 0; j < NTL; j++) {
            const int n = n0 + warp_n * WN + j * 8 + t * 2;
            float* d = acc[i][j];
            float v0 = d[0], v1 = d[1], v2 = d[2], v3 = d[3];
            if (BIAS) {
                const float b0 = bias[n], b1 = bias[n + 1];
                v0 += b0; v1 += b1; v2 += b0; v3 += b1;
            }
            if (OUT16) {
                uint32_t* C2 = (uint32_t*)Cv;
                C2[(size_t)rm * (Nc / 2) + n / 2]       = pk2h(v0, v1);
                C2[(size_t)(rm + 8) * (Nc / 2) + n / 2] = pk2h(v2, v3);
            } else {
                float* C = (float*)Cv;
                *(float2*)&C[(size_t)rm * Nc + n]       = make_float2(v0, v1);
                *(float2*)&C[(size_t)(rm + 8) * Nc + n] = make_float2(v2, v3);
            }
        }
    }
}

// ---------------- neighbor embedding: scalar layers 1-2 (fast gelu) + HMMA layer 3 ----
__global__ void __launch_bounds__(128) nbr_embed_kernel(
    const float* __restrict__ x, const float* __restrict__ xyz,
    const int* __restrict__ knn,
    const float* __restrict__ w1, const float* __restrict__ g1, const float* __restrict__ b1,
    const float* __restrict__ w2, const float* __restrict__ g2, const float* __restrict__ b2,
    const __half* __restrict__ w3t,   // [96n][32k] fp16
    const float* __restrict__ ng, const float* __restrict__ nb,
    float* __restrict__ f, uint32_t* __restrict__ f2)
{
    __shared__ float sw1[7 * 16];
    __shared__ float sg1[16], sb1[16];
    __shared__ float sw2[16 * 32];
    __shared__ float sg2[32], sb2[32];
    __shared__ uint32_t sA[128 * AS];
    __shared__ uint32_t sB[96 * AS];

    const int tid = threadIdx.x;
    for (int i = tid; i < 7 * 16; i += 128) sw1[i] = w1[i];
    if (tid < 16) { sg1[tid] = g1[tid]; sb1[tid] = b1[tid]; }
    for (int i = tid; i < 16 * 32; i += 128) sw2[i] = w2[i];
    if (tid < 32) { sg2[tid] = g2[tid]; sb2[tid] = b2[tid]; }
    for (int e = tid; e < 96 * 4; e += 128) {
        const int row = e >> 2, q = e & 3;
        *(uint4*)&sB[row * AS + q * 4] = *(const uint4*)&w3t[(size_t)row * 32 + q * 8];
    }
    __syncthreads();

    const int n = blockIdx.x * 8 + (tid >> 4);
    const int j = knn[n * KNN + (tid & 15)];

    float v[7];
    v[0] = xyz[j * 3 + 0] - xyz[n * 3 + 0];
    v[1] = xyz[j * 3 + 1] - xyz[n * 3 + 1];
    v[2] = xyz[j * 3 + 2] - xyz[n * 3 + 2];
    v[3] = x[j * 4 + 0];
    v[4] = x[j * 4 + 1];
    v[5] = x[j * 4 + 2];
    v[6] = x[j * 4 + 3];

    float h1[16];
#pragma unroll
    for (int o = 0; o < 16; o++) {
        float s = 0.f;
#pragma unroll
        for (int i = 0; i < 7; i++) s += v[i] * sw1[i * 16 + o];
        h1[o] = gelu_fast(s * sg1[o] + sb1[o]);
    }
    float h2[32];
#pragma unroll
    for (int o = 0; o < 32; o++) {
        float s = 0.f;
#pragma unroll
        for (int i = 0; i < 16; i++) s += h1[i] * sw2[i * 32 + o];
        h2[o] = gelu_fast(s * sg2[o] + sb2[o]);
    }
#pragma unroll
    for (int o = 0; o < 16; o++)
        sA[tid * AS + o] = pk2h(h2[2 * o], h2[2 * o + 1]);
    __syncthreads();

    const uint32_t sAb = smem_u32(sA), sBb = smem_u32(sB);
    const int wid = tid >> 5, lane = tid & 31;
    const int t = lane & 3;
    const uint32_t abase = (((lane & 7) + ((lane >> 3) & 1) * 8) * AS + (lane >> 4) * 4) * 4;
    const uint32_t bbase = ((lane & 7) * AS + (lane >> 3) * 4) * 4;

    uint32_t ah[2][2][4];
#pragma unroll
    for (int i = 0; i < 2; i++)
#pragma unroll
        for (int ks = 0; ks < 2; ks++)
            ldm_x4(ah[i][ks], sAb + abase + ((wid * 32 + i * 16) * AS + ks * 8) * 4);

    const uint32_t rmask = 0x11111111u << t;
#pragma unroll
    for (int jn = 0; jn < 12; jn++) {
        uint32_t b[4];
        ldm_x4(b, sBb + bbase + jn * 8 * AS * 4);
#pragma unroll
        for (int i = 0; i < 2; i++) {
            float d[4] = {0.f, 0.f, 0.f, 0.f};
            mma16816(d, ah[i][0], b);
            mma16816(d, ah[i][1], b + 2);
            float mA = redux_maxf(fmaxf(d[0], d[2]), rmask);
            float mB = redux_maxf(fmaxf(d[1], d[3]), rmask);
            if (lane < 4) {
                const int c = jn * 8 + t * 2;
                const int p = blockIdx.x * 8 + wid * 2 + i;
                const float o0 = mA * ng[c]     + nb[c];
                const float o1 = mB * ng[c + 1] + nb[c + 1];
                f[(size_t)p * 96 + c]     = o0;
                f[(size_t)p * 96 + c + 1] = o1;
                f2[(size_t)p * 48 + (c >> 1)] = pk2h(o0, o1);
            }
        }
    }
}

// ---------------- LFP edge (fp16 y): f += bn(max_k y[knn[n,k]] - y[n]); update shadow ----
__global__ void lfp_edge_kernel(
    const uint32_t* __restrict__ y2, const int* __restrict__ knn,
    const float* __restrict__ g, const float* __restrict__ b,
    float* __restrict__ f, uint32_t* __restrict__ f2)
{
    const int warp = (blockIdx.x * blockDim.x + threadIdx.x) >> 5;
    const int lane = threadIdx.x & 31;
    const int n = warp;
    const int l16 = lane & 15;

    const uint32_t NEG2 = 0xFC00FC00u;   // (-inf, -inf) fp16
    __half2 m0 = *(const __half2*)&NEG2;
    __half2 m1 = m0;
#pragma unroll
    for (int k = 0; k < KNN; k++) {
        const int j = knn[n * KNN + k];
        const uint32_t* yr = y2 + (size_t)j * 48;
        uint32_t v0 = yr[lane];
        m0 = __hmax2(m0, *(__half2*)&v0);
        if (lane < 16) {
            uint32_t v1 = yr[32 + l16];
            m1 = __hmax2(m1, *(__half2*)&v1);
        }
    }
    const uint32_t* yn = y2 + (size_t)n * 48;
    float* fn = f + (size_t)n * DCH;
    uint32_t* fn2 = f2 + (size_t)n * 48;
    {
        uint32_t u = yn[lane];
        __half2 yv = *(__half2*)&u;
        const int c = 2 * lane;
        float2 fv = *(float2*)&fn[c];
        fv.x += (__half2float(__low2half(m0))  - __half2float(__low2half(yv)))  * g[c]     + b[c];
        fv.y += (__half2float(__high2half(m0)) - __half2float(__high2half(yv))) * g[c + 1] + b[c + 1];
        *(float2*)&fn[c] = fv;
        fn2[lane] = pk2h(fv.x, fv.y);
    }
    if (lane < 16) {
        uint32_t u = yn[32 + l16];
        __half2 yv = *(__half2*)&u;
        const int c = 64 + 2 * l16;
        float2 fv = *(float2*)&fn[c];
        fv.x += (__half2float(__low2half(m1))  - __half2float(__low2half(yv)))  * g[c]     + b[c];
        fv.y += (__half2float(__high2half(m1)) - __half2float(__high2half(yv))) * g[c + 1] + b[c + 1];
        *(float2*)&fn[c] = fv;
        fn2[32 + l16] = pk2h(fv.x, fv.y);
    }
}

// ---------------- host ----------------
static inline int smem_bytes(int NT) { return 3 * (128 * AS + NT * AS) * 4; }

extern "C" void kernel_launch(void* const* d_in, const int* in_sizes, int n_in,
                              void* d_out, int out_size)
{
    const float* x      = (const float*)d_in[0];
    const float* xyz    = (const float*)d_in[1];
    const int*   knn    = (const int*)  d_in[2];
    const float* ne_w1  = (const float*)d_in[3];
    const float* ne_g1  = (const float*)d_in[4];
    const float* ne_b1  = (const float*)d_in[5];
    const float* ne_w2  = (const float*)d_in[6];
    const float* ne_g2  = (const float*)d_in[7];
    const float* ne_b2  = (const float*)d_in[8];
    const float* ne_w3  = (const float*)d_in[9];
    const float* nbr_g  = (const float*)d_in[10];
    const float* nbr_b  = (const float*)d_in[11];
    const float* m0_w1  = (const float*)d_in[12];
    const float* m0_b1  = (const float*)d_in[13];
    const float* m0_w2  = (const float*)d_in[14];
    const float* m0_g   = (const float*)d_in[15];
    const float* m0_b   = (const float*)d_in[16];
    const float* lfp_w  = (const float*)d_in[17];
    const float* lfp_g  = (const float*)d_in[18];
    const float* lfp_b  = (const float*)d_in[19];
    const float* ms_w1  = (const float*)d_in[20];
    const float* ms_b1  = (const float*)d_in[21];
    const float* ms_w2  = (const float*)d_in[22];
    const float* ms_g   = (const float*)d_in[23];
    const float* ms_b   = (const float*)d_in[24];
    const float* pp_g   = (const float*)d_in[25];
    const float* pp_b   = (const float*)d_in[26];
    const float* pp_w   = (const float*)d_in[27];
    float* out = (float*)d_out;

    float *f, *hb;
    uint32_t *f2, *y2;
    __half *wh;
    cudaGetSymbolAddress((void**)&f,  g_f);
    cudaGetSymbolAddress((void**)&f2, g_f2);
    cudaGetSymbolAddress((void**)&y2, g_y2);
    cudaGetSymbolAddress((void**)&hb, g_hb);
    cudaGetSymbolAddress((void**)&wh, g_wh);

    const int SM96 = smem_bytes(96);   // 53760
    const int SM64 = smem_bytes(64);   // 46080
    cudaFuncSetAttribute(hmma_gemm<96, true, false>, cudaFuncAttributeMaxDynamicSharedMemorySize, SM96);
    cudaFuncSetAttribute(hmma_gemm<64, false, true>, cudaFuncAttributeMaxDynamicSharedMemorySize, SM64);
    cudaFuncSetAttribute(fused_mlp, cudaFuncAttributeMaxDynamicSharedMemorySize, FUSED_SMEM);

    // weight pre-conversion (transpose + fp16 round; pp_g folded into head W)
    conv_weights<<<(WTOTAL + 255) / 256, 256>>>(lfp_w, m0_w1, ms_w1, m0_w2, ms_w2, pp_w, pp_g, ne_w3);
    head_bias<<<1, HD>>>(pp_b, pp_w, hb);

    // stage 1: neighbor embedding -> f + shadow
    nbr_embed_kernel<<<NPTS / 8, 128>>>(
        x, xyz, knn, ne_w1, ne_g1, ne_b1, ne_w2, ne_g2, ne_b2,
        wh + WOFF_NE, nbr_g, nbr_b, f, f2);

    auto launch_mlp = [&](int j) {
        fused_mlp<<<NPTS / 128, 256, FUSED_SMEM>>>(
            f2,
            wh + WOFF_UP + (size_t)j * 36864,
            wh + WOFF_DOWN + (size_t)j * 36864,
            (j == 0) ? m0_b1 : (ms_b1 + (size_t)(j - 1) * HCH),
            (j == 0) ? m0_g  : (ms_g + (size_t)(j - 1) * DCH),
            (j == 0) ? m0_b  : (ms_b + (size_t)(j - 1) * DCH),
            f, f2);
    };

    launch_mlp(0);
    for (int i = 0; i < 4; i++) {
        // y = f @ lfp_w[i]  (fp16 in, fp16 out)
        hmma_gemm<96, true, false><<<dim3(1, NPTS / 128), 256, SM96>>>(
            f2, wh + WOFF_LFP + (size_t)i * 9216,
            y2, nullptr, DCH);
        // f += bn(max_k y[knn] - y); update shadow
        lfp_edge_kernel<<<NPTS / 8, 256>>>(y2, knn, lfp_g + i * DCH, lfp_b + i * DCH, f, f2);
        if (i & 1) launch_mlp(1 + i / 2);
    }

    // stage 4: out = f2 @ (pp_g*pp_w) + hb
    hmma_gemm<64, false, true><<<dim3(HD / 64, NPTS / 128), 256, SM64>>>(
        f2, wh + WOFF_HEAD,
        out, hb, HD);
}

// round 15
// speedup vs baseline: 1.0591x; 1.0591x over previous
#include <cuda_runtime.h>
#include <cuda_fp16.h>
#include <math.h>
#include <stdint.h>

#define NPTS 65536
#define KNN  16
#define DCH  96
#define HCH  384
#define HD   256

// ---------------- scratch (allocation-free: device globals) ----------------
__device__ float    g_f[(size_t)NPTS * DCH];     // running feature fp32 [N,96]
__device__ uint32_t g_y2[(size_t)NPTS * 48];     // LFP projection, fp16x2 [N,96]

// pre-converted weights: [Nc][K] fp16 (B^T layout, n-major rows)
// LFP 4x(96x96) | UP 3x(384x96) | DOWN 3x(96x384) | HEAD (256x96) | NE3 (96x32)
#define WOFF_LFP   0
#define WOFF_UP    36864
#define WOFF_DOWN  147456
#define WOFF_HEAD  258048
#define WOFF_NE    282624
#define WTOTAL     285696
__device__ __half g_wh[WTOTAL];

__device__ __forceinline__ float gelu_exact(float v) {
    return 0.5f * v * (1.0f + erff(v * 0.70710678118654752440f));
}

__device__ __forceinline__ uint32_t smem_u32(const void* p) {
    uint32_t a;
    asm("{ .reg .u64 t; cvta.to.shared.u64 t, %1; cvt.u32.u64 %0, t; }" : "=r"(a) : "l"(p));
    return a;
}

__device__ __forceinline__ uint32_t pk2h(float x, float y) {
    __half2 h = __floats2half2_rn(x, y);
    return *(uint32_t*)&h;
}

__device__ __forceinline__ void mma16816(float* d, const uint32_t* a, const uint32_t* b) {
    asm volatile(
        "mma.sync.aligned.m16n8k16.row.col.f32.f16.f16.f32 "
        "{%0,%1,%2,%3}, {%4,%5,%6,%7}, {%8,%9}, {%0,%1,%2,%3};"
        : "+f"(d[0]), "+f"(d[1]), "+f"(d[2]), "+f"(d[3])
        : "r"(a[0]), "r"(a[1]), "r"(a[2]), "r"(a[3]), "r"(b[0]), "r"(b[1]));
}

__device__ __forceinline__ void ldm_x4(uint32_t* r, uint32_t addr) {
    asm volatile("ldmatrix.sync.aligned.m8n8.x4.shared.b16 {%0,%1,%2,%3}, [%4];"
        : "=r"(r[0]), "=r"(r[1]), "=r"(r[2]), "=r"(r[3]) : "r"(addr));
}

// float max over an arbitrary lane mask via redux.sync.max.s32 (order-preserving flip)
__device__ __forceinline__ float redux_maxf(float v, uint32_t mask) {
    int u = __float_as_int(v);
    u ^= (u >> 31) & 0x7fffffff;
    int r;
    asm volatile("redux.sync.max.s32 %0, %1, %2;" : "=r"(r) : "r"(u), "r"(mask));
    r ^= (r >> 31) & 0x7fffffff;
    return __int_as_float(r);
}

// =============== weight pre-conversion: fp32 [K][Nc] -> fp16 [Nc][K] ===============
__global__ void conv_weights(const float* __restrict__ lfp_w,
                             const float* __restrict__ m0_w1, const float* __restrict__ ms_w1,
                             const float* __restrict__ m0_w2, const float* __restrict__ ms_w2,
                             const float* __restrict__ pp_w,  const float* __restrict__ ne_w3)
{
    int idx = blockIdx.x * blockDim.x + threadIdx.x;
    if (idx >= WTOTAL) return;
    float v;
    if (idx < WOFF_UP) {                       // LFP: 4 x [96n][96k]
        int i = idx / 9216, r = idx % 9216, n = r / 96, k = r % 96;
        v = lfp_w[i * 9216 + k * 96 + n];
    } else if (idx < WOFF_DOWN) {              // UP: 3 x [384n][96k], src [96][384]
        int t = idx - WOFF_UP, j = t / 36864, r = t % 36864, n = r / 96, k = r % 96;
        const float* src = (j == 0) ? m0_w1 : (ms_w1 + (size_t)(j - 1) * 96 * 384);
        v = src[k * 384 + n];
    } else if (idx < WOFF_HEAD) {              // DOWN: 3 x [96n][384k], src [384][96]
        int t = idx - WOFF_DOWN, j = t / 36864, r = t % 36864, n = r / 384, k = r % 384;
        const float* src = (j == 0) ? m0_w2 : (ms_w2 + (size_t)(j - 1) * 384 * 96);
        v = src[k * 96 + n];
    } else if (idx < WOFF_NE) {                // HEAD: [256n][96k], src [96][256]
        int t = idx - WOFF_HEAD, n = t / 96, k = t % 96;
        v = pp_w[k * 256 + n];
    } else {                                   // NE3: [96n][32k], src [32][96]
        int t = idx - WOFF_NE, n = t / 32, k = t % 32;
        v = ne_w3[k * 96 + n];
    }
    g_wh[idx] = __float2half_rn(v);
}

#define AS   20                    // smem row stride in u32 per 32-k chunk
#define CHP  (128 * AS)            // u32 per chunk-plane for A/H (2560)
#define WCHP (96 * AS)             // u32 per chunk-plane for W  (1920)

// =============== fused MLP: f += bn(gelu(f@W1 + b1) @ W2) ===============
// CTA = 128 points, 256 threads = 8 warps (2M x 4N), warp tile 64 x 24.
#define OFF_H  (3 * CHP)                      // 7680
#define OFF_W1 (OFF_H + 3 * CHP)              // 15360
#define OFF_W2 (OFF_W1 + 3 * WCHP)            // 21120
#define FUSED_SMEM ((OFF_W2 + 3 * WCHP) * 4)  // 107520 B

__global__ void __launch_bounds__(256, 2) fused_mlp(
    const float* __restrict__ F,
    const __half* __restrict__ W1, const __half* __restrict__ W2,  // [384][96], [96][384]
    const float* __restrict__ b1,
    const float* __restrict__ bng, const float* __restrict__ bnb,
    float* __restrict__ Fout)
{
    extern __shared__ uint32_t sm[];
    const uint32_t sb = smem_u32(sm);

    const int tid = threadIdx.x, wid = tid >> 5, lane = tid & 31;
    const int g = lane >> 2, t = lane & 3;
    const int warp_m = wid >> 2, warp_n = wid & 3;
    const int m0 = blockIdx.x * 128;

    const uint32_t aoff = ((warp_m * 64 + (lane & 7) + ((lane >> 3) & 1) * 8) * AS + (lane >> 4) * 4) * 4;
    const uint32_t boff = ((warp_n * 24 + (lane & 7)) * AS + (lane >> 3) * 4) * 4;

    // ---- load f tile [128 x 96] -> fp16 chunked smem ----
#pragma unroll
    for (int it = 0; it < 12; it++) {
        const int e = it * 256 + tid;
        const int row = e / 24, qq = e % 24, col = qq * 4;
        float4 v = *(const float4*)&F[(size_t)(m0 + row) * 96 + col];
        const int chunk = col >> 5, q = (col & 31) >> 2;
        *(uint2*)(sm + chunk * CHP + row * AS + q * 2) =
            make_uint2(pk2h(v.x, v.y), pk2h(v.z, v.w));
    }

    float out[4][3][4] = {};

    auto gemm_chunk = [&](uint32_t aB, uint32_t wB, float acc[4][3][4]) {
        uint32_t bh[3][4];
#pragma unroll
        for (int j = 0; j < 3; j++)
            ldm_x4(bh[j], wB + boff + j * 8 * AS * 4);
#pragma unroll
        for (int ks = 0; ks < 2; ks++) {
#pragma unroll
            for (int i = 0; i < 4; i++) {
                uint32_t ah[4];
                ldm_x4(ah, aB + aoff + (i * 16 * AS + ks * 8) * 4);
#pragma unroll
                for (int j = 0; j < 3; j++)
                    mma16816(acc[i][j], ah, &bh[j][ks * 2]);
            }
        }
    };

    for (int s = 0; s < 4; s++) {
        // ---- stage W1 slice s [96n x 96k] and W2 slice s [96n x 96k] ----
#pragma unroll
        for (int e = tid; e < 96 * 12; e += 256) {
            const int row = e / 12, qu = e % 12;
            const int chunk = qu >> 2, q4 = (qu & 3) * 4;
            {
                const size_t gi = (size_t)(s * 96 + row) * 96 + qu * 8;
                *(uint4*)(sm + OFF_W1 + chunk * WCHP + row * AS + q4) = *(const uint4*)&W1[gi];
            }
            {
                const size_t gi = (size_t)row * 384 + s * 96 + qu * 8;
                *(uint4*)(sm + OFF_W2 + chunk * WCHP + row * AS + q4) = *(const uint4*)&W2[gi];
            }
        }
        __syncthreads();

        // ---- GEMM1: hid = f @ W1[s] ----
        float hid[4][3][4] = {};
#pragma unroll
        for (int kc = 0; kc < 3; kc++)
            gemm_chunk(sb + kc * CHP * 4, sb + (OFF_W1 + kc * WCHP) * 4, hid);

        // ---- bias + gelu -> fp16 H tile ----
#pragma unroll
        for (int i = 0; i < 4; i++) {
            const int rm = warp_m * 64 + i * 16 + g;
#pragma unroll
            for (int j = 0; j < 3; j++) {
                const int nn = warp_n * 24 + j * 8 + t * 2;
                const float b0 = b1[s * 96 + nn], b1v = b1[s * 96 + nn + 1];
                const uint32_t h01 = pk2h(gelu_exact(hid[i][j][0] + b0), gelu_exact(hid[i][j][1] + b1v));
                const uint32_t h23 = pk2h(gelu_exact(hid[i][j][2] + b0), gelu_exact(hid[i][j][3] + b1v));
                const int chunk = nn >> 5, q2 = (nn & 31) >> 1;
                uint32_t* p = sm + OFF_H + chunk * CHP;
                p[rm * AS + q2]       = h01;
                p[(rm + 8) * AS + q2] = h23;
            }
        }
        __syncthreads();

        // ---- GEMM2 partial: out += H @ W2[:, s*96:(s+1)*96] ----
#pragma unroll
        for (int kc = 0; kc < 3; kc++)
            gemm_chunk(sb + (OFF_H + kc * CHP) * 4, sb + (OFF_W2 + kc * WCHP) * 4, out);

        __syncthreads();
    }

    // ---- epilogue: f += out * bng + bnb ----
#pragma unroll
    for (int i = 0; i < 4; i++) {
        const int rm = m0 + warp_m * 64 + i * 16 + g;
#pragma unroll
        for (int j = 0; j < 3; j++) {
            const int n = warp_n * 24 + j * 8 + t * 2;
            const float s0 = bng[n], s1 = bng[n + 1];
            const float q0 = bnb[n], q1 = bnb[n + 1];
            float* p0 = &Fout[(size_t)rm * 96 + n];
            float* p1 = &Fout[(size_t)(rm + 8) * 96 + n];
            float2 c0 = *(float2*)p0;
            float2 c1 = *(float2*)p1;
            *(float2*)p0 = make_float2(c0.x + out[i][j][0] * s0 + q0,
                                       c0.y + out[i][j][1] * s1 + q1);
            *(float2*)p1 = make_float2(c1.x + out[i][j][2] * s0 + q0,
                                       c1.y + out[i][j][3] * s1 + q1);
        }
    }
}

// =============== HMMA GEMM (standalone, for LFP proj + head) ===============
// 256 threads = 8 warps (2M x 4N), warp tile 64 x NT/4. Double-buffered k32.
// fp16 A and W, 1 MMA per fragment pair. OUT16: write packed half2.
template <bool ABN, int NT, int KTOT, bool OUT16>
__global__ void __launch_bounds__(256, 2) hmma_gemm(
    const float* __restrict__ A,
    const __half* __restrict__ W,
    void* __restrict__ Cv,
    const float* __restrict__ gA, const float* __restrict__ bA,
    int Nc)
{
    constexpr int WN   = NT / 4;
    constexpr int NTL  = WN / 8;
    constexpr int NC   = KTOT / 32;
    constexpr int ASZ  = 128 * AS;
    constexpr int BSZ  = NT * AS;
    constexpr int BUFU = ASZ + BSZ;

    extern __shared__ uint32_t sm[];
    const uint32_t sb = smem_u32(sm);

    const int tid = threadIdx.x, wid = tid >> 5, lane = tid & 31;
    const int g = lane >> 2, t = lane & 3;
    const int warp_m = wid >> 2, warp_n = wid & 3;
    const int m0 = blockIdx.y * 128, n0 = blockIdx.x * NT;

    float acc[4][NTL][4] = {};
    const float* Ablk = A + (size_t)m0 * KTOT;

    const uint32_t aoff = ((warp_m * 64 + (lane & 7) + ((lane >> 3) & 1) * 8) * AS + (lane >> 4) * 4) * 4;
    const uint32_t boff = ((warp_n * WN + (lane & 7)) * AS + (lane >> 3) * 4) * 4;

    auto load_chunk = [&](int kc, uint32_t* buf) {
        uint32_t* Ah = buf;
        uint32_t* Bh = buf + ASZ;
        const int kb = kc * 32;
#pragma unroll
        for (int it = 0; it < 4; it++) {
            const int e = it * 256 + tid;
            const int row = e >> 3, q = e & 7, col = q * 4;
            float4 v = *(const float4*)&Ablk[(size_t)row * KTOT + kb + col];
            if (ABN) {
                const int k = kb + col;
                v.x = v.x * gA[k]     + bA[k];
                v.y = v.y * gA[k + 1] + bA[k + 1];
                v.z = v.z * gA[k + 2] + bA[k + 2];
                v.w = v.w * gA[k + 3] + bA[k + 3];
            }
            *(uint2*)&Ah[row * AS + q * 2] = make_uint2(pk2h(v.x, v.y), pk2h(v.z, v.w));
        }
#pragma unroll
        for (int e = tid; e < NT * 4; e += 256) {
            const int row = e >> 2, q = e & 3;
            *(uint4*)&Bh[row * AS + q * 4] = *(const uint4*)&W[(size_t)(n0 + row) * KTOT + kb + q * 8];
        }
    };

    auto compute = [&](uint32_t bufbase) {
        const uint32_t ahB = bufbase + aoff;
        const uint32_t bhB = bufbase + ASZ * 4 + boff;
        uint32_t bh[NTL][4];
#pragma unroll
        for (int j = 0; j < NTL; j++)
            ldm_x4(bh[j], bhB + j * 8 * AS * 4);
#pragma unroll
        for (int ks = 0; ks < 2; ks++) {
#pragma unroll
            for (int i = 0; i < 4; i++) {
                uint32_t ah[4];
                ldm_x4(ah, ahB + (i * 16 * AS + ks * 8) * 4);
#pragma unroll
                for (int j = 0; j < NTL; j++)
                    mma16816(acc[i][j], ah, &bh[j][ks * 2]);
            }
        }
    };

    load_chunk(0, sm);
    __syncthreads();
#pragma unroll
    for (int kc = 0; kc < NC; kc++) {
        if (kc + 1 < NC) load_chunk(kc + 1, sm + ((kc + 1) & 1) * BUFU);
        compute(sb + (uint32_t)(kc & 1) * BUFU * 4);
        __syncthreads();
    }

#pragma unroll
    for (int i = 0; i < 4; i++) {
        const int rm = m0 + warp_m * 64 + i * 16 + g;
#pragma unroll
        for (int j = 0; j < NTL; j++) {
            const int n = n0 + warp_n * WN + j * 8 + t * 2;
            float* d = acc[i][j];
            if (OUT16) {
                uint32_t* C2 = (uint32_t*)Cv;
                C2[(size_t)rm * (Nc / 2) + n / 2]       = pk2h(d[0], d[1]);
                C2[(size_t)(rm + 8) * (Nc / 2) + n / 2] = pk2h(d[2], d[3]);
            } else {
                float* C = (float*)Cv;
                *(float2*)&C[(size_t)rm * Nc + n]       = make_float2(d[0], d[1]);
                *(float2*)&C[(size_t)(rm + 8) * Nc + n] = make_float2(d[2], d[3]);
            }
        }
    }
}

// ---------------- neighbor embedding: scalar layers 1-2 + HMMA layer 3 + in-fragment maxpool ----
__global__ void __launch_bounds__(128) nbr_embed_kernel(
    const float* __restrict__ x, const float* __restrict__ xyz,
    const int* __restrict__ knn,
    const float* __restrict__ w1, const float* __restrict__ g1, const float* __restrict__ b1,
    const float* __restrict__ w2, const float* __restrict__ g2, const float* __restrict__ b2,
    const __half* __restrict__ w3t,   // [96n][32k] fp16
    const float* __restrict__ ng, const float* __restrict__ nb,
    float* __restrict__ f)
{
    __shared__ float sw1[7 * 16];
    __shared__ float sg1[16], sb1[16];
    __shared__ float sw2[16 * 32];
    __shared__ float sg2[32], sb2[32];
    __shared__ uint32_t sA[128 * AS];
    __shared__ uint32_t sB[96 * AS];

    const int tid = threadIdx.x;
    for (int i = tid; i < 7 * 16; i += 128) sw1[i] = w1[i];
    if (tid < 16) { sg1[tid] = g1[tid]; sb1[tid] = b1[tid]; }
    for (int i = tid; i < 16 * 32; i += 128) sw2[i] = w2[i];
    if (tid < 32) { sg2[tid] = g2[tid]; sb2[tid] = b2[tid]; }
    for (int e = tid; e < 96 * 4; e += 128) {
        const int row = e >> 2, q = e & 3;
        *(uint4*)&sB[row * AS + q * 4] = *(const uint4*)&w3t[(size_t)row * 32 + q * 8];
    }
    __syncthreads();

    const int n = blockIdx.x * 8 + (tid >> 4);
    const int j = knn[n * KNN + (tid & 15)];

    float v[7];
    v[0] = xyz[j * 3 + 0] - xyz[n * 3 + 0];
    v[1] = xyz[j * 3 + 1] - xyz[n * 3 + 1];
    v[2] = xyz[j * 3 + 2] - xyz[n * 3 + 2];
    v[3] = x[j * 4 + 0];
    v[4] = x[j * 4 + 1];
    v[5] = x[j * 4 + 2];
    v[6] = x[j * 4 + 3];

    float h1[16];
#pragma unroll
    for (int o = 0; o < 16; o++) {
        float s = 0.f;
#pragma unroll
        for (int i = 0; i < 7; i++) s += v[i] * sw1[i * 16 + o];
        h1[o] = gelu_exact(s * sg1[o] + sb1[o]);
    }
    float h2[32];
#pragma unroll
    for (int o = 0; o < 32; o++) {
        float s = 0.f;
#pragma unroll
        for (int i = 0; i < 16; i++) s += h1[i] * sw2[i * 32 + o];
        h2[o] = gelu_exact(s * sg2[o] + sb2[o]);
    }
#pragma unroll
    for (int o = 0; o < 16; o++)
        sA[tid * AS + o] = pk2h(h2[2 * o], h2[2 * o + 1]);
    __syncthreads();

    const uint32_t sAb = smem_u32(sA), sBb = smem_u32(sB);
    const int wid = tid >> 5, lane = tid & 31;
    const int t = lane & 3;
    const uint32_t abase = (((lane & 7) + ((lane >> 3) & 1) * 8) * AS + (lane >> 4) * 4) * 4;
    const uint32_t bbase = ((lane & 7) * AS + (lane >> 3) * 4) * 4;

    uint32_t ah[2][2][4];
#pragma unroll
    for (int i = 0; i < 2; i++)
#pragma unroll
        for (int ks = 0; ks < 2; ks++)
            ldm_x4(ah[i][ks], sAb + abase + ((wid * 32 + i * 16) * AS + ks * 8) * 4);

    const uint32_t rmask = 0x11111111u << t;
#pragma unroll
    for (int jn = 0; jn < 12; jn++) {
        uint32_t b[4];
        ldm_x4(b, sBb + bbase + jn * 8 * AS * 4);
#pragma unroll
        for (int i = 0; i < 2; i++) {
            float d[4] = {0.f, 0.f, 0.f, 0.f};
            mma16816(d, ah[i][0], b);
            mma16816(d, ah[i][1], b + 2);
            float mA = redux_maxf(fmaxf(d[0], d[2]), rmask);
            float mB = redux_maxf(fmaxf(d[1], d[3]), rmask);
            if (lane < 4) {
                const int c = jn * 8 + t * 2;
                const int p = blockIdx.x * 8 + wid * 2 + i;
                f[(size_t)p * 96 + c]     = mA * ng[c]     + nb[c];
                f[(size_t)p * 96 + c + 1] = mB * ng[c + 1] + nb[c + 1];
            }
        }
    }
}

// ---------------- LFP edge (fp16 y, balanced 24-lane uint2 gather) ----------------
// f += bn(max_k y[knn[n,k]] - y[n]).  Row = 48 half2 words; lane l (<24) owns
// words 2l,2l+1 = channels 4l..4l+3. One 8B load per neighbor per lane.
__global__ void lfp_edge_kernel(
    const uint32_t* __restrict__ y2, const int* __restrict__ knn,
    const float* __restrict__ g, const float* __restrict__ b,
    float* __restrict__ f)
{
    const int warp = (blockIdx.x * blockDim.x + threadIdx.x) >> 5;
    const int lane = threadIdx.x & 31;
    const int n = warp;
    if (lane >= 24) return;

    const uint32_t NEG2 = 0xFC00FC00u;   // (-inf, -inf) fp16
    __half2 m0 = *(const __half2*)&NEG2;
    __half2 m1 = m0;
#pragma unroll
    for (int k = 0; k < KNN; k++) {
        const int j = knn[n * KNN + k];
        const uint2 v = *(const uint2*)(y2 + (size_t)j * 48 + lane * 2);
        m0 = __hmax2(m0, *(const __half2*)&v.x);
        m1 = __hmax2(m1, *(const __half2*)&v.y);
    }
    const uint2 u = *(const uint2*)(y2 + (size_t)n * 48 + lane * 2);
    const __half2 y0 = *(const __half2*)&u.x;
    const __half2 y1 = *(const __half2*)&u.y;
    const int c = lane * 4;
    float4 fv = *(float4*)&f[(size_t)n * DCH + c];
    fv.x += (__half2float(__low2half(m0))  - __half2float(__low2half(y0)))  * g[c]     + b[c];
    fv.y += (__half2float(__high2half(m0)) - __half2float(__high2half(y0))) * g[c + 1] + b[c + 1];
    fv.z += (__half2float(__low2half(m1))  - __half2float(__low2half(y1)))  * g[c + 2] + b[c + 2];
    fv.w += (__half2float(__high2half(m1)) - __half2float(__high2half(y1))) * g[c + 3] + b[c + 3];
    *(float4*)&f[(size_t)n * DCH + c] = fv;
}

// ---------------- host ----------------
// smem bytes: 2 buffers * (2*128*AS + NT*AS) u32 * 4B
static inline int smem_bytes(int NT) { return 2 * (2 * 128 * AS + NT * AS) * 4; }

extern "C" void kernel_launch(void* const* d_in, const int* in_sizes, int n_in,
                              void* d_out, int out_size)
{
    const float* x      = (const float*)d_in[0];
    const float* xyz    = (const float*)d_in[1];
    const int*   knn    = (const int*)  d_in[2];
    const float* ne_w1  = (const float*)d_in[3];
    const float* ne_g1  = (const float*)d_in[4];
    const float* ne_b1  = (const float*)d_in[5];
    const float* ne_w2  = (const float*)d_in[6];
    const float* ne_g2  = (const float*)d_in[7];
    const float* ne_b2  = (const float*)d_in[8];
    const float* ne_w3  = (const float*)d_in[9];
    const float* nbr_g  = (const float*)d_in[10];
    const float* nbr_b  = (const float*)d_in[11];
    const float* m0_w1  = (const float*)d_in[12];
    const float* m0_b1  = (const float*)d_in[13];
    const float* m0_w2  = (const float*)d_in[14];
    const float* m0_g   = (const float*)d_in[15];
    const float* m0_b   = (const float*)d_in[16];
    const float* lfp_w  = (const float*)d_in[17];
    const float* lfp_g  = (const float*)d_in[18];
    const float* lfp_b  = (const float*)d_in[19];
    const float* ms_w1  = (const float*)d_in[20];
    const float* ms_b1  = (const float*)d_in[21];
    const float* ms_w2  = (const float*)d_in[22];
    const float* ms_g   = (const float*)d_in[23];
    const float* ms_b   = (const float*)d_in[24];
    const float* pp_g   = (const float*)d_in[25];
    const float* pp_b   = (const float*)d_in[26];
    const float* pp_w   = (const float*)d_in[27];
    float* out = (float*)d_out;

    float *f;
    uint32_t *y2;
    __half *wh;
    cudaGetSymbolAddress((void**)&f, g_f);
    cudaGetSymbolAddress((void**)&y2, g_y2);
    cudaGetSymbolAddress((void**)&wh, g_wh);

    const int SM96 = smem_bytes(96);   // 56320
    const int SM64 = smem_bytes(64);   // 51200
    cudaFuncSetAttribute(hmma_gemm<false, 96, 96, true>, cudaFuncAttributeMaxDynamicSharedMemorySize, SM96);
    cudaFuncSetAttribute(hmma_gemm<true, 64, 96, false>, cudaFuncAttributeMaxDynamicSharedMemorySize, SM64);
    cudaFuncSetAttribute(fused_mlp, cudaFuncAttributeMaxDynamicSharedMemorySize, FUSED_SMEM);

    // weight pre-conversion (transpose + fp16 round)
    conv_weights<<<(WTOTAL + 255) / 256, 256>>>(lfp_w, m0_w1, ms_w1, m0_w2, ms_w2, pp_w, ne_w3);

    // stage 1: neighbor embedding -> f [N,96]
    nbr_embed_kernel<<<NPTS / 8, 128>>>(
        x, xyz, knn, ne_w1, ne_g1, ne_b1, ne_w2, ne_g2, ne_b2,
        wh + WOFF_NE, nbr_g, nbr_b, f);

    auto launch_mlp = [&](int j) {
        fused_mlp<<<NPTS / 128, 256, FUSED_SMEM>>>(
            f,
            wh + WOFF_UP + (size_t)j * 36864,
            wh + WOFF_DOWN + (size_t)j * 36864,
            (j == 0) ? m0_b1 : (ms_b1 + (size_t)(j - 1) * HCH),
            (j == 0) ? m0_g  : (ms_g + (size_t)(j - 1) * DCH),
            (j == 0) ? m0_b  : (ms_b + (size_t)(j - 1) * DCH),
            f);
    };

    launch_mlp(0);
    for (int i = 0; i < 4; i++) {
        // y = f @ lfp_w[i]  (fp16 output)
        hmma_gemm<false, 96, 96, true><<<dim3(1, NPTS / 128), 256, SM96>>>(
            f, wh + WOFF_LFP + (size_t)i * 9216,
            y2, nullptr, nullptr, DCH);
        // f += bn(max_k y[knn] - y)
        lfp_edge_kernel<<<NPTS / 8, 256>>>(y2, knn, lfp_g + i * DCH, lfp_b + i * DCH, f);
        if (i & 1) launch_mlp(1 + i / 2);
    }

    // stage 4: out = bn(f) @ pp_w (BN folded into A load)
    hmma_gemm<true, 64, 96, false><<<dim3(HD / 64, NPTS / 128), 256, SM64>>>(
        f, wh + WOFF_HEAD,
        out, pp_g, pp_b, HD);
}

// round 16
// speedup vs baseline: 1.0717x; 1.0119x over previous
#include <cuda_runtime.h>
#include <cuda_fp16.h>
#include <math.h>
#include <stdint.h>

#define NPTS 65536
#define KNN  16
#define DCH  96
#define HCH  384
#define HD   256

// ---------------- scratch (allocation-free: device globals) ----------------
__device__ float    g_f[(size_t)NPTS * DCH];     // running feature fp32 [N,96]
__device__ uint32_t g_y2[(size_t)NPTS * 48];     // LFP projection, fp16x2 [N,96]

// pre-converted weights: [Nc][K] fp16 (B^T layout, n-major rows)
// LFP 4x(96x96) | UP 3x(384x96) | DOWN 3x(96x384) | HEAD (256x96) | NE3 (96x32)
#define WOFF_LFP   0
#define WOFF_UP    36864
#define WOFF_DOWN  147456
#define WOFF_HEAD  258048
#define WOFF_NE    282624
#define WTOTAL     285696
__device__ __half g_wh[WTOTAL];

__device__ __forceinline__ float gelu_exact(float v) {
    return 0.5f * v * (1.0f + erff(v * 0.70710678118654752440f));
}

__device__ __forceinline__ uint32_t smem_u32(const void* p) {
    uint32_t a;
    asm("{ .reg .u64 t; cvta.to.shared.u64 t, %1; cvt.u32.u64 %0, t; }" : "=r"(a) : "l"(p));
    return a;
}

__device__ __forceinline__ uint32_t pk2h(float x, float y) {
    __half2 h = __floats2half2_rn(x, y);
    return *(uint32_t*)&h;
}

__device__ __forceinline__ void mma16816(float* d, const uint32_t* a, const uint32_t* b) {
    asm volatile(
        "mma.sync.aligned.m16n8k16.row.col.f32.f16.f16.f32 "
        "{%0,%1,%2,%3}, {%4,%5,%6,%7}, {%8,%9}, {%0,%1,%2,%3};"
        : "+f"(d[0]), "+f"(d[1]), "+f"(d[2]), "+f"(d[3])
        : "r"(a[0]), "r"(a[1]), "r"(a[2]), "r"(a[3]), "r"(b[0]), "r"(b[1]));
}

__device__ __forceinline__ void ldm_x4(uint32_t* r, uint32_t addr) {
    asm volatile("ldmatrix.sync.aligned.m8n8.x4.shared.b16 {%0,%1,%2,%3}, [%4];"
        : "=r"(r[0]), "=r"(r[1]), "=r"(r[2]), "=r"(r[3]) : "r"(addr));
}

// float max over an arbitrary lane mask via redux.sync.max.s32 (order-preserving flip)
__device__ __forceinline__ float redux_maxf(float v, uint32_t mask) {
    int u = __float_as_int(v);
    u ^= (u >> 31) & 0x7fffffff;
    int r;
    asm volatile("redux.sync.max.s32 %0, %1, %2;" : "=r"(r) : "r"(u), "r"(mask));
    r ^= (r >> 31) & 0x7fffffff;
    return __int_as_float(r);
}

// =============== weight pre-conversion: fp32 [K][Nc] -> fp16 [Nc][K] ===============
__global__ void conv_weights(const float* __restrict__ lfp_w,
                             const float* __restrict__ m0_w1, const float* __restrict__ ms_w1,
                             const float* __restrict__ m0_w2, const float* __restrict__ ms_w2,
                             const float* __restrict__ pp_w,  const float* __restrict__ ne_w3)
{
    int idx = blockIdx.x * blockDim.x + threadIdx.x;
    if (idx >= WTOTAL) return;
    float v;
    if (idx < WOFF_UP) {                       // LFP: 4 x [96n][96k]
        int i = idx / 9216, r = idx % 9216, n = r / 96, k = r % 96;
        v = lfp_w[i * 9216 + k * 96 + n];
    } else if (idx < WOFF_DOWN) {              // UP: 3 x [384n][96k], src [96][384]
        int t = idx - WOFF_UP, j = t / 36864, r = t % 36864, n = r / 96, k = r % 96;
        const float* src = (j == 0) ? m0_w1 : (ms_w1 + (size_t)(j - 1) * 96 * 384);
        v = src[k * 384 + n];
    } else if (idx < WOFF_HEAD) {              // DOWN: 3 x [96n][384k], src [384][96]
        int t = idx - WOFF_DOWN, j = t / 36864, r = t % 36864, n = r / 384, k = r % 384;
        const float* src = (j == 0) ? m0_w2 : (ms_w2 + (size_t)(j - 1) * 384 * 96);
        v = src[k * 96 + n];
    } else if (idx < WOFF_NE) {                // HEAD: [256n][96k], src [96][256]
        int t = idx - WOFF_HEAD, n = t / 96, k = t % 96;
        v = pp_w[k * 256 + n];
    } else {                                   // NE3: [96n][32k], src [32][96]
        int t = idx - WOFF_NE, n = t / 32, k = t % 32;
        v = ne_w3[k * 96 + n];
    }
    g_wh[idx] = __float2half_rn(v);
}

#define AS   20                    // smem row stride in u32 per 32-k chunk
#define CHP  (128 * AS)            // u32 per chunk-plane for A (2560)
#define WCHP (96 * AS)             // u32 per chunk-plane for W (1920)

// =============== fused MLP: f += bn(gelu(f@W1 + b1) @ W2) ===============
// CTA = 128 points, 256 threads = 8 warps; warp = 16 rows x FULL 96 cols.
// GEMM1 output fragments are re-used directly as GEMM2 A-fragments (C-frag == A-frag
// layout identity) -> no hidden-tile smem round trip; 2 barriers per slice.
#define OFF_W1 (3 * CHP)                      // 7680
#define OFF_W2 (OFF_W1 + 3 * WCHP)            // 13440
#define FUSED_SMEM ((OFF_W2 + 3 * WCHP) * 4)  // 76800 B

__global__ void __launch_bounds__(256, 2) fused_mlp(
    const float* __restrict__ F,
    const __half* __restrict__ W1, const __half* __restrict__ W2,  // [384][96], [96][384]
    const float* __restrict__ b1,
    const float* __restrict__ bng, const float* __restrict__ bnb,
    float* __restrict__ Fout)
{
    extern __shared__ uint32_t sm[];
    const uint32_t sb = smem_u32(sm);

    const int tid = threadIdx.x, wid = tid >> 5, lane = tid & 31;
    const int g = lane >> 2, t = lane & 3;
    const int m0 = blockIdx.x * 128;

    // A lane offset (m16 tile at rows wid*16..wid*16+15)
    const uint32_t aoff = ((wid * 16 + (lane & 7) + ((lane >> 3) & 1) * 8) * AS + (lane >> 4) * 4) * 4;
    // B lane offset (n-tile base added per j)
    const uint32_t bLane = ((lane & 7) * AS + (lane >> 3) * 4) * 4;

    // ---- load f tile [128 x 96] -> fp16 chunked smem ----
#pragma unroll
    for (int it = 0; it < 12; it++) {
        const int e = it * 256 + tid;
        const int row = e / 24, qq = e % 24, col = qq * 4;
        float4 v = *(const float4*)&F[(size_t)(m0 + row) * 96 + col];
        const int chunk = col >> 5, q = (col & 31) >> 2;
        *(uint2*)(sm + chunk * CHP + row * AS + q * 2) =
            make_uint2(pk2h(v.x, v.y), pk2h(v.z, v.w));
    }

    float out[12][4] = {};

    for (int s = 0; s < 4; s++) {
        // ---- stage W1 slice s [96n x 96k] and W2 slice s [96n x 96k] ----
#pragma unroll
        for (int e = tid; e < 96 * 12; e += 256) {
            const int row = e / 12, qu = e % 12;
            const int chunk = qu >> 2, q4 = (qu & 3) * 4;
            {
                const size_t gi = (size_t)(s * 96 + row) * 96 + qu * 8;
                *(uint4*)(sm + OFF_W1 + chunk * WCHP + row * AS + q4) = *(const uint4*)&W1[gi];
            }
            {
                const size_t gi = (size_t)row * 384 + s * 96 + qu * 8;
                *(uint4*)(sm + OFF_W2 + chunk * WCHP + row * AS + q4) = *(const uint4*)&W2[gi];
            }
        }
        __syncthreads();

        // ---- GEMM1: hid(16x96) = f(16x96) @ W1[s]^T, all in registers ----
        float hid[12][4] = {};
#pragma unroll
        for (int kc = 0; kc < 3; kc++) {
            uint32_t a0[4], a1[4];
            ldm_x4(a0, sb + (uint32_t)kc * CHP * 4 + aoff);
            ldm_x4(a1, sb + (uint32_t)kc * CHP * 4 + aoff + 8 * 4);
#pragma unroll
            for (int j = 0; j < 12; j++) {
                uint32_t b[4];
                ldm_x4(b, sb + (uint32_t)(OFF_W1 + kc * WCHP) * 4 + bLane + (uint32_t)j * 8 * AS * 4);
                mma16816(hid[j], a0, &b[0]);
                mma16816(hid[j], a1, &b[2]);
            }
        }

        // ---- bias + gelu in registers, pack into GEMM2 A-fragments ----
#pragma unroll
        for (int j = 0; j < 12; j++) {
            const int nn = j * 8 + t * 2;
            const float c0 = b1[s * 96 + nn], c1 = b1[s * 96 + nn + 1];
            hid[j][0] = gelu_exact(hid[j][0] + c0);
            hid[j][1] = gelu_exact(hid[j][1] + c1);
            hid[j][2] = gelu_exact(hid[j][2] + c0);
            hid[j][3] = gelu_exact(hid[j][3] + c1);
        }
        uint32_t ap[6][4];
#pragma unroll
        for (int kk = 0; kk < 6; kk++) {
            ap[kk][0] = pk2h(hid[2 * kk][0],     hid[2 * kk][1]);
            ap[kk][1] = pk2h(hid[2 * kk][2],     hid[2 * kk][3]);
            ap[kk][2] = pk2h(hid[2 * kk + 1][0], hid[2 * kk + 1][1]);
            ap[kk][3] = pk2h(hid[2 * kk + 1][2], hid[2 * kk + 1][3]);
        }

        // ---- GEMM2 partial: out += gelu_hid @ W2[:, s*96:(s+1)*96]^T ----
#pragma unroll
        for (int kc = 0; kc < 3; kc++) {
#pragma unroll
            for (int j = 0; j < 12; j++) {
                uint32_t b[4];
                ldm_x4(b, sb + (uint32_t)(OFF_W2 + kc * WCHP) * 4 + bLane + (uint32_t)j * 8 * AS * 4);
                mma16816(out[j], ap[2 * kc], &b[0]);
                mma16816(out[j], ap[2 * kc + 1], &b[2]);
            }
        }
        __syncthreads();   // done reading W1/W2 for this slice
    }

    // ---- epilogue: f += out * bng + bnb ----
#pragma unroll
    for (int j = 0; j < 12; j++) {
        const int rm = m0 + wid * 16 + g;
        const int n = j * 8 + t * 2;
        const float s0 = bng[n], s1 = bng[n + 1];
        const float q0 = bnb[n], q1 = bnb[n + 1];
        float* p0 = &Fout[(size_t)rm * 96 + n];
        float* p1 = &Fout[(size_t)(rm + 8) * 96 + n];
        float2 c0 = *(float2*)p0;
        float2 c1 = *(float2*)p1;
        *(float2*)p0 = make_float2(c0.x + out[j][0] * s0 + q0,
                                   c0.y + out[j][1] * s1 + q1);
        *(float2*)p1 = make_float2(c1.x + out[j][2] * s0 + q0,
                                   c1.y + out[j][3] * s1 + q1);
    }
}

// =============== HMMA GEMM (standalone, for LFP proj + head) ===============
// 256 threads = 8 warps (2M x 4N), warp tile 64 x NT/4. Double-buffered k32.
template <bool ABN, int NT, int KTOT, bool OUT16>
__global__ void __launch_bounds__(256, 2) hmma_gemm(
    const float* __restrict__ A,
    const __half* __restrict__ W,
    void* __restrict__ Cv,
    const float* __restrict__ gA, const float* __restrict__ bA,
    int Nc)
{
    constexpr int WN   = NT / 4;
    constexpr int NTL  = WN / 8;
    constexpr int NC   = KTOT / 32;
    constexpr int ASZ  = 128 * AS;
    constexpr int BSZ  = NT * AS;
    constexpr int BUFU = ASZ + BSZ;

    extern __shared__ uint32_t sm[];
    const uint32_t sb = smem_u32(sm);

    const int tid = threadIdx.x, wid = tid >> 5, lane = tid & 31;
    const int g = lane >> 2, t = lane & 3;
    const int warp_m = wid >> 2, warp_n = wid & 3;
    const int m0 = blockIdx.y * 128, n0 = blockIdx.x * NT;

    float acc[4][NTL][4] = {};
    const float* Ablk = A + (size_t)m0 * KTOT;

    const uint32_t aoff = ((warp_m * 64 + (lane & 7) + ((lane >> 3) & 1) * 8) * AS + (lane >> 4) * 4) * 4;
    const uint32_t boff = ((warp_n * WN + (lane & 7)) * AS + (lane >> 3) * 4) * 4;

    auto load_chunk = [&](int kc, uint32_t* buf) {
        uint32_t* Ah = buf;
        uint32_t* Bh = buf + ASZ;
        const int kb = kc * 32;
#pragma unroll
        for (int it = 0; it < 4; it++) {
            const int e = it * 256 + tid;
            const int row = e >> 3, q = e & 7, col = q * 4;
            float4 v = *(const float4*)&Ablk[(size_t)row * KTOT + kb + col];
            if (ABN) {
                const int k = kb + col;
                v.x = v.x * gA[k]     + bA[k];
                v.y = v.y * gA[k + 1] + bA[k + 1];
                v.z = v.z * gA[k + 2] + bA[k + 2];
                v.w = v.w * gA[k + 3] + bA[k + 3];
            }
            *(uint2*)&Ah[row * AS + q * 2] = make_uint2(pk2h(v.x, v.y), pk2h(v.z, v.w));
        }
#pragma unroll
        for (int e = tid; e < NT * 4; e += 256) {
            const int row = e >> 2, q = e & 3;
            *(uint4*)&Bh[row * AS + q * 4] = *(const uint4*)&W[(size_t)(n0 + row) * KTOT + kb + q * 8];
        }
    };

    auto compute = [&](uint32_t bufbase) {
        const uint32_t ahB = bufbase + aoff;
        const uint32_t bhB = bufbase + ASZ * 4 + boff;
        uint32_t bh[NTL][4];
#pragma unroll
        for (int j = 0; j < NTL; j++)
            ldm_x4(bh[j], bhB + j * 8 * AS * 4);
#pragma unroll
        for (int ks = 0; ks < 2; ks++) {
#pragma unroll
            for (int i = 0; i < 4; i++) {
                uint32_t ah[4];
                ldm_x4(ah, ahB + (i * 16 * AS + ks * 8) * 4);
#pragma unroll
                for (int j = 0; j < NTL; j++)
                    mma16816(acc[i][j], ah, &bh[j][ks * 2]);
            }
        }
    };

    load_chunk(0, sm);
    __syncthreads();
#pragma unroll
    for (int kc = 0; kc < NC; kc++) {
        if (kc + 1 < NC) load_chunk(kc + 1, sm + ((kc + 1) & 1) * BUFU);
        compute(sb + (uint32_t)(kc & 1) * BUFU * 4);
        __syncthreads();
    }

#pragma unroll
    for (int i = 0; i < 4; i++) {
        const int rm = m0 + warp_m * 64 + i * 16 + g;
#pragma unroll
        for (int j = 0; j < NTL; j++) {
            const int n = n0 + warp_n * WN + j * 8 + t * 2;
            float* d = acc[i][j];
            if (OUT16) {
                uint32_t* C2 = (uint32_t*)Cv;
                C2[(size_t)rm * (Nc / 2) + n / 2]       = pk2h(d[0], d[1]);
                C2[(size_t)(rm + 8) * (Nc / 2) + n / 2] = pk2h(d[2], d[3]);
            } else {
                float* C = (float*)Cv;
                *(float2*)&C[(size_t)rm * Nc + n]       = make_float2(d[0], d[1]);
                *(float2*)&C[(size_t)(rm + 8) * Nc + n] = make_float2(d[2], d[3]);
            }
        }
    }
}

// ---------------- neighbor embedding: scalar layers 1-2 + HMMA layer 3 + in-fragment maxpool ----
__global__ void __launch_bounds__(128) nbr_embed_kernel(
    const float* __restrict__ x, const float* __restrict__ xyz,
    const int* __restrict__ knn,
    const float* __restrict__ w1, const float* __restrict__ g1, const float* __restrict__ b1,
    const float* __restrict__ w2, const float* __restrict__ g2, const float* __restrict__ b2,
    const __half* __restrict__ w3t,   // [96n][32k] fp16
    const float* __restrict__ ng, const float* __restrict__ nb,
    float* __restrict__ f)
{
    __shared__ float sw1[7 * 16];
    __shared__ float sg1[16], sb1[16];
    __shared__ float sw2[16 * 32];
    __shared__ float sg2[32], sb2[32];
    __shared__ uint32_t sA[128 * AS];
    __shared__ uint32_t sB[96 * AS];

    const int tid = threadIdx.x;
    for (int i = tid; i < 7 * 16; i += 128) sw1[i] = w1[i];
    if (tid < 16) { sg1[tid] = g1[tid]; sb1[tid] = b1[tid]; }
    for (int i = tid; i < 16 * 32; i += 128) sw2[i] = w2[i];
    if (tid < 32) { sg2[tid] = g2[tid]; sb2[tid] = b2[tid]; }
    for (int e = tid; e < 96 * 4; e += 128) {
        const int row = e >> 2, q = e & 3;
        *(uint4*)&sB[row * AS + q * 4] = *(const uint4*)&w3t[(size_t)row * 32 + q * 8];
    }
    __syncthreads();

    const int n = blockIdx.x * 8 + (tid >> 4);
    const int j = knn[n * KNN + (tid & 15)];

    float v[7];
    v[0] = xyz[j * 3 + 0] - xyz[n * 3 + 0];
    v[1] = xyz[j * 3 + 1] - xyz[n * 3 + 1];
    v[2] = xyz[j * 3 + 2] - xyz[n * 3 + 2];
    v[3] = x[j * 4 + 0];
    v[4] = x[j * 4 + 1];
    v[5] = x[j * 4 + 2];
    v[6] = x[j * 4 + 3];

    float h1[16];
#pragma unroll
    for (int o = 0; o < 16; o++) {
        float s = 0.f;
#pragma unroll
        for (int i = 0; i < 7; i++) s += v[i] * sw1[i * 16 + o];
        h1[o] = gelu_exact(s * sg1[o] + sb1[o]);
    }
    float h2[32];
#pragma unroll
    for (int o = 0; o < 32; o++) {
        float s = 0.f;
#pragma unroll
        for (int i = 0; i < 16; i++) s += h1[i] * sw2[i * 32 + o];
        h2[o] = gelu_exact(s * sg2[o] + sb2[o]);
    }
#pragma unroll
    for (int o = 0; o < 16; o++)
        sA[tid * AS + o] = pk2h(h2[2 * o], h2[2 * o + 1]);
    __syncthreads();

    const uint32_t sAb = smem_u32(sA), sBb = smem_u32(sB);
    const int wid = tid >> 5, lane = tid & 31;
    const int t = lane & 3;
    const uint32_t abase = (((lane & 7) + ((lane >> 3) & 1) * 8) * AS + (lane >> 4) * 4) * 4;
    const uint32_t bbase = ((lane & 7) * AS + (lane >> 3) * 4) * 4;

    uint32_t ah[2][2][4];
#pragma unroll
    for (int i = 0; i < 2; i++)
#pragma unroll
        for (int ks = 0; ks < 2; ks++)
            ldm_x4(ah[i][ks], sAb + abase + ((wid * 32 + i * 16) * AS + ks * 8) * 4);

    const uint32_t rmask = 0x11111111u << t;
#pragma unroll
    for (int jn = 0; jn < 12; jn++) {
        uint32_t b[4];
        ldm_x4(b, sBb + bbase + jn * 8 * AS * 4);
#pragma unroll
        for (int i = 0; i < 2; i++) {
            float d[4] = {0.f, 0.f, 0.f, 0.f};
            mma16816(d, ah[i][0], b);
            mma16816(d, ah[i][1], b + 2);
            float mA = redux_maxf(fmaxf(d[0], d[2]), rmask);
            float mB = redux_maxf(fmaxf(d[1], d[3]), rmask);
            if (lane < 4) {
                const int c = jn * 8 + t * 2;
                const int p = blockIdx.x * 8 + wid * 2 + i;
                f[(size_t)p * 96 + c]     = mA * ng[c]     + nb[c];
                f[(size_t)p * 96 + c + 1] = mB * ng[c + 1] + nb[c + 1];
            }
        }
    }
}

// ---------------- LFP edge (fp16 y, balanced 24-lane uint2 gather) ----------------
__global__ void lfp_edge_kernel(
    const uint32_t* __restrict__ y2, const int* __restrict__ knn,
    const float* __restrict__ g, const float* __restrict__ b,
    float* __restrict__ f)
{
    const int warp = (blockIdx.x * blockDim.x + threadIdx.x) >> 5;
    const int lane = threadIdx.x & 31;
    const int n = warp;
    if (lane >= 24) return;

    const uint32_t NEG2 = 0xFC00FC00u;   // (-inf, -inf) fp16
    __half2 m0 = *(const __half2*)&NEG2;
    __half2 m1 = m0;
#pragma unroll
    for (int k = 0; k < KNN; k++) {
        const int j = knn[n * KNN + k];
        const uint2 v = *(const uint2*)(y2 + (size_t)j * 48 + lane * 2);
        m0 = __hmax2(m0, *(const __half2*)&v.x);
        m1 = __hmax2(m1, *(const __half2*)&v.y);
    }
    const uint2 u = *(const uint2*)(y2 + (size_t)n * 48 + lane * 2);
    const __half2 y0 = *(const __half2*)&u.x;
    const __half2 y1 = *(const __half2*)&u.y;
    const int c = lane * 4;
    float4 fv = *(float4*)&f[(size_t)n * DCH + c];
    fv.x += (__half2float(__low2half(m0))  - __half2float(__low2half(y0)))  * g[c]     + b[c];
    fv.y += (__half2float(__high2half(m0)) - __half2float(__high2half(y0))) * g[c + 1] + b[c + 1];
    fv.z += (__half2float(__low2half(m1))  - __half2float(__low2half(y1)))  * g[c + 2] + b[c + 2];
    fv.w += (__half2float(__high2half(m1)) - __half2float(__high2half(y1))) * g[c + 3] + b[c + 3];
    *(float4*)&f[(size_t)n * DCH + c] = fv;
}

// ---------------- host ----------------
static inline int smem_bytes(int NT) { return 2 * (2 * 128 * AS + NT * AS) * 4; }

extern "C" void kernel_launch(void* const* d_in, const int* in_sizes, int n_in,
                              void* d_out, int out_size)
{
    const float* x      = (const float*)d_in[0];
    const float* xyz    = (const float*)d_in[1];
    const int*   knn    = (const int*)  d_in[2];
    const float* ne_w1  = (const float*)d_in[3];
    const float* ne_g1  = (const float*)d_in[4];
    const float* ne_b1  = (const float*)d_in[5];
    const float* ne_w2  = (const float*)d_in[6];
    const float* ne_g2  = (const float*)d_in[7];
    const float* ne_b2  = (const float*)d_in[8];
    const float* ne_w3  = (const float*)d_in[9];
    const float* nbr_g  = (const float*)d_in[10];
    const float* nbr_b  = (const float*)d_in[11];
    const float* m0_w1  = (const float*)d_in[12];
    const float* m0_b1  = (const float*)d_in[13];
    const float* m0_w2  = (const float*)d_in[14];
    const float* m0_g   = (const float*)d_in[15];
    const float* m0_b   = (const float*)d_in[16];
    const float* lfp_w  = (const float*)d_in[17];
    const float* lfp_g  = (const float*)d_in[18];
    const float* lfp_b  = (const float*)d_in[19];
    const float* ms_w1  = (const float*)d_in[20];
    const float* ms_b1  = (const float*)d_in[21];
    const float* ms_w2  = (const float*)d_in[22];
    const float* ms_g   = (const float*)d_in[23];
    const float* ms_b   = (const float*)d_in[24];
    const float* pp_g   = (const float*)d_in[25];
    const float* pp_b   = (const float*)d_in[26];
    const float* pp_w   = (const float*)d_in[27];
    float* out = (float*)d_out;

    float *f;
    uint32_t *y2;
    __half *wh;
    cudaGetSymbolAddress((void**)&f, g_f);
    cudaGetSymbolAddress((void**)&y2, g_y2);
    cudaGetSymbolAddress((void**)&wh, g_wh);

    const int SM96 = smem_bytes(96);   // 56320
    const int SM64 = smem_bytes(64);   // 51200
    cudaFuncSetAttribute(hmma_gemm<false, 96, 96, true>, cudaFuncAttributeMaxDynamicSharedMemorySize, SM96);
    cudaFuncSetAttribute(hmma_gemm<true, 64, 96, false>, cudaFuncAttributeMaxDynamicSharedMemorySize, SM64);
    cudaFuncSetAttribute(fused_mlp, cudaFuncAttributeMaxDynamicSharedMemorySize, FUSED_SMEM);

    // weight pre-conversion (transpose + fp16 round)
    conv_weights<<<(WTOTAL + 255) / 256, 256>>>(lfp_w, m0_w1, ms_w1, m0_w2, ms_w2, pp_w, ne_w3);

    // stage 1: neighbor embedding -> f [N,96]
    nbr_embed_kernel<<<NPTS / 8, 128>>>(
        x, xyz, knn, ne_w1, ne_g1, ne_b1, ne_w2, ne_g2, ne_b2,
        wh + WOFF_NE, nbr_g, nbr_b, f);

    auto launch_mlp = [&](int j) {
        fused_mlp<<<NPTS / 128, 256, FUSED_SMEM>>>(
            f,
            wh + WOFF_UP + (size_t)j * 36864,
            wh + WOFF_DOWN + (size_t)j * 36864,
            (j == 0) ? m0_b1 : (ms_b1 + (size_t)(j - 1) * HCH),
            (j == 0) ? m0_g  : (ms_g + (size_t)(j - 1) * DCH),
            (j == 0) ? m0_b  : (ms_b + (size_t)(j - 1) * DCH),
            f);
    };

    launch_mlp(0);
    for (int i = 0; i < 4; i++) {
        // y = f @ lfp_w[i]  (fp16 output)
        hmma_gemm<false, 96, 96, true><<<dim3(1, NPTS / 128), 256, SM96>>>(
            f, wh + WOFF_LFP + (size_t)i * 9216,
            y2, nullptr, nullptr, DCH);
        // f += bn(max_k y[knn] - y)
        lfp_edge_kernel<<<NPTS / 8, 256>>>(y2, knn, lfp_g + i * DCH, lfp_b + i * DCH, f);
        if (i & 1) launch_mlp(1 + i / 2);
    }

    // stage 4: out = bn(f) @ pp_w (BN folded into A load)
    hmma_gemm<true, 64, 96, false><<<dim3(HD / 64, NPTS / 128), 256, SM64>>>(
        f, wh + WOFF_HEAD,
        out, pp_g, pp_b, HD);
}

// round 17
// speedup vs baseline: 1.0855x; 1.0129x over previous
#include <cuda_runtime.h>
#include <cuda_fp16.h>
#include <math.h>
#include <stdint.h>

#define NPTS 65536
#define KNN  16
#define DCH  96
#define HCH  384
#define HD   256

// ---------------- scratch (allocation-free: device globals) ----------------
__device__ float    g_f[(size_t)NPTS * DCH];     // running feature fp32 [N,96]
__device__ uint32_t g_y2[(size_t)NPTS * 48];     // LFP projection, fp16x2 [N,96]

// pre-converted weights: [Nc][K] fp16 (B^T layout, n-major rows)
// LFP 4x(96x96) | UP 3x(384x96) | DOWN 3x(96x384) | HEAD (256x96) | NE3 (96x32)
#define WOFF_LFP   0
#define WOFF_UP    36864
#define WOFF_DOWN  147456
#define WOFF_HEAD  258048
#define WOFF_NE    282624
#define WTOTAL     285696
__device__ __half g_wh[WTOTAL];

__device__ __forceinline__ float gelu_exact(float v) {
    return 0.5f * v * (1.0f + erff(v * 0.70710678118654752440f));
}

__device__ __forceinline__ uint32_t smem_u32(const void* p) {
    uint32_t a;
    asm("{ .reg .u64 t; cvta.to.shared.u64 t, %1; cvt.u32.u64 %0, t; }" : "=r"(a) : "l"(p));
    return a;
}

__device__ __forceinline__ uint32_t pk2h(float x, float y) {
    __half2 h = __floats2half2_rn(x, y);
    return *(uint32_t*)&h;
}

__device__ __forceinline__ void mma16816(float* d, const uint32_t* a, const uint32_t* b) {
    asm volatile(
        "mma.sync.aligned.m16n8k16.row.col.f32.f16.f16.f32 "
        "{%0,%1,%2,%3}, {%4,%5,%6,%7}, {%8,%9}, {%0,%1,%2,%3};"
        : "+f"(d[0]), "+f"(d[1]), "+f"(d[2]), "+f"(d[3])
        : "r"(a[0]), "r"(a[1]), "r"(a[2]), "r"(a[3]), "r"(b[0]), "r"(b[1]));
}

__device__ __forceinline__ void ldm_x4(uint32_t* r, uint32_t addr) {
    asm volatile("ldmatrix.sync.aligned.m8n8.x4.shared.b16 {%0,%1,%2,%3}, [%4];"
        : "=r"(r[0]), "=r"(r[1]), "=r"(r[2]), "=r"(r[3]) : "r"(addr));
}

// float max over an arbitrary lane mask via redux.sync.max.s32 (order-preserving flip)
__device__ __forceinline__ float redux_maxf(float v, uint32_t mask) {
    int u = __float_as_int(v);
    u ^= (u >> 31) & 0x7fffffff;
    int r;
    asm volatile("redux.sync.max.s32 %0, %1, %2;" : "=r"(r) : "r"(u), "r"(mask));
    r ^= (r >> 31) & 0x7fffffff;
    return __int_as_float(r);
}

// =============== weight pre-conversion: fp32 [K][Nc] -> fp16 [Nc][K] ===============
__global__ void conv_weights(const float* __restrict__ lfp_w,
                             const float* __restrict__ m0_w1, const float* __restrict__ ms_w1,
                             const float* __restrict__ m0_w2, const float* __restrict__ ms_w2,
                             const float* __restrict__ pp_w,  const float* __restrict__ ne_w3)
{
    int idx = blockIdx.x * blockDim.x + threadIdx.x;
    if (idx >= WTOTAL) return;
    float v;
    if (idx < WOFF_UP) {                       // LFP: 4 x [96n][96k]
        int i = idx / 9216, r = idx % 9216, n = r / 96, k = r % 96;
        v = lfp_w[i * 9216 + k * 96 + n];
    } else if (idx < WOFF_DOWN) {              // UP: 3 x [384n][96k], src [96][384]
        int t = idx - WOFF_UP, j = t / 36864, r = t % 36864, n = r / 96, k = r % 96;
        const float* src = (j == 0) ? m0_w1 : (ms_w1 + (size_t)(j - 1) * 96 * 384);
        v = src[k * 384 + n];
    } else if (idx < WOFF_HEAD) {              // DOWN: 3 x [96n][384k], src [384][96]
        int t = idx - WOFF_DOWN, j = t / 36864, r = t % 36864, n = r / 384, k = r % 384;
        const float* src = (j == 0) ? m0_w2 : (ms_w2 + (size_t)(j - 1) * 384 * 96);
        v = src[k * 96 + n];
    } else if (idx < WOFF_NE) {                // HEAD: [256n][96k], src [96][256]
        int t = idx - WOFF_HEAD, n = t / 96, k = t % 96;
        v = pp_w[k * 256 + n];
    } else {                                   // NE3: [96n][32k], src [32][96]
        int t = idx - WOFF_NE, n = t / 32, k = t % 32;
        v = ne_w3[k * 96 + n];
    }
    g_wh[idx] = __float2half_rn(v);
}

#define AS   20                    // smem row stride in u32 per 32-k chunk
#define CHP  (128 * AS)            // u32 per chunk-plane for A (2560)
#define WCHP (96 * AS)             // u32 per chunk-plane for W (1920)

// =============== fused MLP: f += bn(gelu(f@W1 + b1) @ W2) ===============
// CTA = 128 points, 256 threads = 8 warps; warp = 16 rows x FULL 96 cols.
// GEMM1 output fragments re-used directly as GEMM2 A-fragments.
#define OFF_W1 (3 * CHP)                      // 7680
#define OFF_W2 (OFF_W1 + 3 * WCHP)            // 13440
#define FUSED_SMEM ((OFF_W2 + 3 * WCHP) * 4)  // 76800 B

__global__ void __launch_bounds__(256, 2) fused_mlp(
    const float* __restrict__ F,
    const __half* __restrict__ W1, const __half* __restrict__ W2,  // [384][96], [96][384]
    const float* __restrict__ b1,
    const float* __restrict__ bng, const float* __restrict__ bnb,
    float* __restrict__ Fout)
{
    extern __shared__ uint32_t sm[];
    const uint32_t sb = smem_u32(sm);

    const int tid = threadIdx.x, wid = tid >> 5, lane = tid & 31;
    const int g = lane >> 2, t = lane & 3;
    const int m0 = blockIdx.x * 128;

    const uint32_t aoff = ((wid * 16 + (lane & 7) + ((lane >> 3) & 1) * 8) * AS + (lane >> 4) * 4) * 4;
    const uint32_t bLane = ((lane & 7) * AS + (lane >> 3) * 4) * 4;

    // ---- load f tile [128 x 96] -> fp16 chunked smem ----
#pragma unroll
    for (int it = 0; it < 12; it++) {
        const int e = it * 256 + tid;
        const int row = e / 24, qq = e % 24, col = qq * 4;
        float4 v = *(const float4*)&F[(size_t)(m0 + row) * 96 + col];
        const int chunk = col >> 5, q = (col & 31) >> 2;
        *(uint2*)(sm + chunk * CHP + row * AS + q * 2) =
            make_uint2(pk2h(v.x, v.y), pk2h(v.z, v.w));
    }

    float out[12][4] = {};

    for (int s = 0; s < 4; s++) {
        // ---- stage W1 slice s [96n x 96k] and W2 slice s [96n x 96k] ----
#pragma unroll
        for (int e = tid; e < 96 * 12; e += 256) {
            const int row = e / 12, qu = e % 12;
            const int chunk = qu >> 2, q4 = (qu & 3) * 4;
            {
                const size_t gi = (size_t)(s * 96 + row) * 96 + qu * 8;
                *(uint4*)(sm + OFF_W1 + chunk * WCHP + row * AS + q4) = *(const uint4*)&W1[gi];
            }
            {
                const size_t gi = (size_t)row * 384 + s * 96 + qu * 8;
                *(uint4*)(sm + OFF_W2 + chunk * WCHP + row * AS + q4) = *(const uint4*)&W2[gi];
            }
        }
        __syncthreads();

        // ---- GEMM1: hid(16x96) = f(16x96) @ W1[s]^T, all in registers ----
        float hid[12][4] = {};
#pragma unroll
        for (int kc = 0; kc < 3; kc++) {
            uint32_t a0[4], a1[4];
            ldm_x4(a0, sb + (uint32_t)kc * CHP * 4 + aoff);
            ldm_x4(a1, sb + (uint32_t)kc * CHP * 4 + aoff + 8 * 4);
#pragma unroll
            for (int j = 0; j < 12; j++) {
                uint32_t b[4];
                ldm_x4(b, sb + (uint32_t)(OFF_W1 + kc * WCHP) * 4 + bLane + (uint32_t)j * 8 * AS * 4);
                mma16816(hid[j], a0, &b[0]);
                mma16816(hid[j], a1, &b[2]);
            }
        }

        // ---- bias + gelu in registers, pack into GEMM2 A-fragments ----
#pragma unroll
        for (int j = 0; j < 12; j++) {
            const int nn = j * 8 + t * 2;
            const float c0 = b1[s * 96 + nn], c1 = b1[s * 96 + nn + 1];
            hid[j][0] = gelu_exact(hid[j][0] + c0);
            hid[j][1] = gelu_exact(hid[j][1] + c1);
            hid[j][2] = gelu_exact(hid[j][2] + c0);
            hid[j][3] = gelu_exact(hid[j][3] + c1);
        }
        uint32_t ap[6][4];
#pragma unroll
        for (int kk = 0; kk < 6; kk++) {
            ap[kk][0] = pk2h(hid[2 * kk][0],     hid[2 * kk][1]);
            ap[kk][1] = pk2h(hid[2 * kk][2],     hid[2 * kk][3]);
            ap[kk][2] = pk2h(hid[2 * kk + 1][0], hid[2 * kk + 1][1]);
            ap[kk][3] = pk2h(hid[2 * kk + 1][2], hid[2 * kk + 1][3]);
        }

        // ---- GEMM2 partial: out += gelu_hid @ W2[:, s*96:(s+1)*96]^T ----
#pragma unroll
        for (int kc = 0; kc < 3; kc++) {
#pragma unroll
            for (int j = 0; j < 12; j++) {
                uint32_t b[4];
                ldm_x4(b, sb + (uint32_t)(OFF_W2 + kc * WCHP) * 4 + bLane + (uint32_t)j * 8 * AS * 4);
                mma16816(out[j], ap[2 * kc], &b[0]);
                mma16816(out[j], ap[2 * kc + 1], &b[2]);
            }
        }
        __syncthreads();   // done reading W1/W2 for this slice
    }

    // ---- epilogue: f += out * bng + bnb ----
#pragma unroll
    for (int j = 0; j < 12; j++) {
        const int rm = m0 + wid * 16 + g;
        const int n = j * 8 + t * 2;
        const float s0 = bng[n], s1 = bng[n + 1];
        const float q0 = bnb[n], q1 = bnb[n + 1];
        float* p0 = &Fout[(size_t)rm * 96 + n];
        float* p1 = &Fout[(size_t)(rm + 8) * 96 + n];
        float2 c0 = *(float2*)p0;
        float2 c1 = *(float2*)p1;
        *(float2*)p0 = make_float2(c0.x + out[j][0] * s0 + q0,
                                   c0.y + out[j][1] * s1 + q1);
        *(float2*)p1 = make_float2(c1.x + out[j][2] * s0 + q0,
                                   c1.y + out[j][3] * s1 + q1);
    }
}

// =============== HMMA GEMM (standalone, for LFP proj + head) ===============
// 256 threads = 8 warps (2M x 4N), warp tile 64 x NT/4. Double-buffered k32.
template <bool ABN, int NT, int KTOT, bool OUT16>
__global__ void __launch_bounds__(256, 2) hmma_gemm(
    const float* __restrict__ A,
    const __half* __restrict__ W,
    void* __restrict__ Cv,
    const float* __restrict__ gA, const float* __restrict__ bA,
    int Nc)
{
    constexpr int WN   = NT / 4;
    constexpr int NTL  = WN / 8;
    constexpr int NC   = KTOT / 32;
    constexpr int ASZ  = 128 * AS;
    constexpr int BSZ  = NT * AS;
    constexpr int BUFU = ASZ + BSZ;

    extern __shared__ uint32_t sm[];
    const uint32_t sb = smem_u32(sm);

    const int tid = threadIdx.x, wid = tid >> 5, lane = tid & 31;
    const int g = lane >> 2, t = lane & 3;
    const int warp_m = wid >> 2, warp_n = wid & 3;
    const int m0 = blockIdx.y * 128, n0 = blockIdx.x * NT;

    float acc[4][NTL][4] = {};
    const float* Ablk = A + (size_t)m0 * KTOT;

    const uint32_t aoff = ((warp_m * 64 + (lane & 7) + ((lane >> 3) & 1) * 8) * AS + (lane >> 4) * 4) * 4;
    const uint32_t boff = ((warp_n * WN + (lane & 7)) * AS + (lane >> 3) * 4) * 4;

    auto load_chunk = [&](int kc, uint32_t* buf) {
        uint32_t* Ah = buf;
        uint32_t* Bh = buf + ASZ;
        const int kb = kc * 32;
#pragma unroll
        for (int it = 0; it < 4; it++) {
            const int e = it * 256 + tid;
            const int row = e >> 3, q = e & 7, col = q * 4;
            float4 v = *(const float4*)&Ablk[(size_t)row * KTOT + kb + col];
            if (ABN) {
                const int k = kb + col;
                v.x = v.x * gA[k]     + bA[k];
                v.y = v.y * gA[k + 1] + bA[k + 1];
                v.z = v.z * gA[k + 2] + bA[k + 2];
                v.w = v.w * gA[k + 3] + bA[k + 3];
            }
            *(uint2*)&Ah[row * AS + q * 2] = make_uint2(pk2h(v.x, v.y), pk2h(v.z, v.w));
        }
#pragma unroll
        for (int e = tid; e < NT * 4; e += 256) {
            const int row = e >> 2, q = e & 3;
            *(uint4*)&Bh[row * AS + q * 4] = *(const uint4*)&W[(size_t)(n0 + row) * KTOT + kb + q * 8];
        }
    };

    auto compute = [&](uint32_t bufbase) {
        const uint32_t ahB = bufbase + aoff;
        const uint32_t bhB = bufbase + ASZ * 4 + boff;
        uint32_t bh[NTL][4];
#pragma unroll
        for (int j = 0; j < NTL; j++)
            ldm_x4(bh[j], bhB + j * 8 * AS * 4);
#pragma unroll
        for (int ks = 0; ks < 2; ks++) {
#pragma unroll
            for (int i = 0; i < 4; i++) {
                uint32_t ah[4];
                ldm_x4(ah, ahB + (i * 16 * AS + ks * 8) * 4);
#pragma unroll
                for (int j = 0; j < NTL; j++)
                    mma16816(acc[i][j], ah, &bh[j][ks * 2]);
            }
        }
    };

    load_chunk(0, sm);
    __syncthreads();
#pragma unroll
    for (int kc = 0; kc < NC; kc++) {
        if (kc + 1 < NC) load_chunk(kc + 1, sm + ((kc + 1) & 1) * BUFU);
        compute(sb + (uint32_t)(kc & 1) * BUFU * 4);
        __syncthreads();
    }

#pragma unroll
    for (int i = 0; i < 4; i++) {
        const int rm = m0 + warp_m * 64 + i * 16 + g;
#pragma unroll
        for (int j = 0; j < NTL; j++) {
            const int n = n0 + warp_n * WN + j * 8 + t * 2;
            float* d = acc[i][j];
            if (OUT16) {
                uint32_t* C2 = (uint32_t*)Cv;
                C2[(size_t)rm * (Nc / 2) + n / 2]       = pk2h(d[0], d[1]);
                C2[(size_t)(rm + 8) * (Nc / 2) + n / 2] = pk2h(d[2], d[3]);
            } else {
                float* C = (float*)Cv;
                *(float2*)&C[(size_t)rm * Nc + n]       = make_float2(d[0], d[1]);
                *(float2*)&C[(size_t)(rm + 8) * Nc + n] = make_float2(d[2], d[3]);
            }
        }
    }
}

// ---------------- neighbor embedding: scalar layers 1-2 + HMMA layer 3 + in-fragment maxpool ----
__global__ void __launch_bounds__(128) nbr_embed_kernel(
    const float* __restrict__ x, const float* __restrict__ xyz,
    const int* __restrict__ knn,
    const float* __restrict__ w1, const float* __restrict__ g1, const float* __restrict__ b1,
    const float* __restrict__ w2, const float* __restrict__ g2, const float* __restrict__ b2,
    const __half* __restrict__ w3t,   // [96n][32k] fp16
    const float* __restrict__ ng, const float* __restrict__ nb,
    float* __restrict__ f)
{
    __shared__ float sw1[7 * 16];
    __shared__ float sg1[16], sb1[16];
    __shared__ float sw2[16 * 32];
    __shared__ float sg2[32], sb2[32];
    __shared__ uint32_t sA[128 * AS];
    __shared__ uint32_t sB[96 * AS];

    const int tid = threadIdx.x;
    for (int i = tid; i < 7 * 16; i += 128) sw1[i] = w1[i];
    if (tid < 16) { sg1[tid] = g1[tid]; sb1[tid] = b1[tid]; }
    for (int i = tid; i < 16 * 32; i += 128) sw2[i] = w2[i];
    if (tid < 32) { sg2[tid] = g2[tid]; sb2[tid] = b2[tid]; }
    for (int e = tid; e < 96 * 4; e += 128) {
        const int row = e >> 2, q = e & 3;
        *(uint4*)&sB[row * AS + q * 4] = *(const uint4*)&w3t[(size_t)row * 32 + q * 8];
    }
    __syncthreads();

    const int n = blockIdx.x * 8 + (tid >> 4);
    const int j = knn[n * KNN + (tid & 15)];

    float v[7];
    v[0] = xyz[j * 3 + 0] - xyz[n * 3 + 0];
    v[1] = xyz[j * 3 + 1] - xyz[n * 3 + 1];
    v[2] = xyz[j * 3 + 2] - xyz[n * 3 + 2];
    v[3] = x[j * 4 + 0];
    v[4] = x[j * 4 + 1];
    v[5] = x[j * 4 + 2];
    v[6] = x[j * 4 + 3];

    float h1[16];
#pragma unroll
    for (int o = 0; o < 16; o++) {
        float s = 0.f;
#pragma unroll
        for (int i = 0; i < 7; i++) s += v[i] * sw1[i * 16 + o];
        h1[o] = gelu_exact(s * sg1[o] + sb1[o]);
    }
    float h2[32];
#pragma unroll
    for (int o = 0; o < 32; o++) {
        float s = 0.f;
#pragma unroll
        for (int i = 0; i < 16; i++) s += h1[i] * sw2[i * 32 + o];
        h2[o] = gelu_exact(s * sg2[o] + sb2[o]);
    }
#pragma unroll
    for (int o = 0; o < 16; o++)
        sA[tid * AS + o] = pk2h(h2[2 * o], h2[2 * o + 1]);
    __syncthreads();

    const uint32_t sAb = smem_u32(sA), sBb = smem_u32(sB);
    const int wid = tid >> 5, lane = tid & 31;
    const int t = lane & 3;
    const uint32_t abase = (((lane & 7) + ((lane >> 3) & 1) * 8) * AS + (lane >> 4) * 4) * 4;
    const uint32_t bbase = ((lane & 7) * AS + (lane >> 3) * 4) * 4;

    uint32_t ah[2][2][4];
#pragma unroll
    for (int i = 0; i < 2; i++)
#pragma unroll
        for (int ks = 0; ks < 2; ks++)
            ldm_x4(ah[i][ks], sAb + abase + ((wid * 32 + i * 16) * AS + ks * 8) * 4);

    const uint32_t rmask = 0x11111111u << t;
#pragma unroll
    for (int jn = 0; jn < 12; jn++) {
        uint32_t b[4];
        ldm_x4(b, sBb + bbase + jn * 8 * AS * 4);
#pragma unroll
        for (int i = 0; i < 2; i++) {
            float d[4] = {0.f, 0.f, 0.f, 0.f};
            mma16816(d, ah[i][0], b);
            mma16816(d, ah[i][1], b + 2);
            float mA = redux_maxf(fmaxf(d[0], d[2]), rmask);
            float mB = redux_maxf(fmaxf(d[1], d[3]), rmask);
            if (lane < 4) {
                const int c = jn * 8 + t * 2;
                const int p = blockIdx.x * 8 + wid * 2 + i;
                f[(size_t)p * 96 + c]     = mA * ng[c]     + nb[c];
                f[(size_t)p * 96 + c + 1] = mB * ng[c + 1] + nb[c + 1];
            }
        }
    }
}

// ---------------- LFP edge (fp16 y, flat-indexed: 1 thread = 1 (point, 8B seg)) ----------------
// f += bn(max_k y[knn[n,k]] - y[n]).  Row = 48 half2 words = 24 segments of uint2;
// thread handles channels 4*seg..4*seg+3 of point n. All 32 lanes active.
__global__ void lfp_edge_kernel(
    const uint32_t* __restrict__ y2, const int* __restrict__ knn,
    const float* __restrict__ g, const float* __restrict__ b,
    float* __restrict__ f)
{
    const int item = blockIdx.x * 256 + threadIdx.x;   // < NPTS*24
    const int n = item / 24;
    const int seg = item - n * 24;

    const uint32_t NEG2 = 0xFC00FC00u;   // (-inf, -inf) fp16
    __half2 m0 = *(const __half2*)&NEG2;
    __half2 m1 = m0;
#pragma unroll
    for (int k = 0; k < KNN; k++) {
        const int j = knn[n * KNN + k];
        const uint2 v = *(const uint2*)(y2 + (size_t)j * 48 + seg * 2);
        m0 = __hmax2(m0, *(const __half2*)&v.x);
        m1 = __hmax2(m1, *(const __half2*)&v.y);
    }
    const uint2 u = *(const uint2*)(y2 + (size_t)n * 48 + seg * 2);
    const __half2 y0 = *(const __half2*)&u.x;
    const __half2 y1 = *(const __half2*)&u.y;
    const int c = seg * 4;
    float4 fv = *(float4*)&f[(size_t)n * DCH + c];
    fv.x += (__half2float(__low2half(m0))  - __half2float(__low2half(y0)))  * g[c]     + b[c];
    fv.y += (__half2float(__high2half(m0)) - __half2float(__high2half(y0))) * g[c + 1] + b[c + 1];
    fv.z += (__half2float(__low2half(m1))  - __half2float(__low2half(y1)))  * g[c + 2] + b[c + 2];
    fv.w += (__half2float(__high2half(m1)) - __half2float(__high2half(y1))) * g[c + 3] + b[c + 3];
    *(float4*)&f[(size_t)n * DCH + c] = fv;
}

// ---------------- host ----------------
static inline int smem_bytes(int NT) { return 2 * (2 * 128 * AS + NT * AS) * 4; }

extern "C" void kernel_launch(void* const* d_in, const int* in_sizes, int n_in,
                              void* d_out, int out_size)
{
    const float* x      = (const float*)d_in[0];
    const float* xyz    = (const float*)d_in[1];
    const int*   knn    = (const int*)  d_in[2];
    const float* ne_w1  = (const float*)d_in[3];
    const float* ne_g1  = (const float*)d_in[4];
    const float* ne_b1  = (const float*)d_in[5];
    const float* ne_w2  = (const float*)d_in[6];
    const float* ne_g2  = (const float*)d_in[7];
    const float* ne_b2  = (const float*)d_in[8];
    const float* ne_w3  = (const float*)d_in[9];
    const float* nbr_g  = (const float*)d_in[10];
    const float* nbr_b  = (const float*)d_in[11];
    const float* m0_w1  = (const float*)d_in[12];
    const float* m0_b1  = (const float*)d_in[13];
    const float* m0_w2  = (const float*)d_in[14];
    const float* m0_g   = (const float*)d_in[15];
    const float* m0_b   = (const float*)d_in[16];
    const float* lfp_w  = (const float*)d_in[17];
    const float* lfp_g  = (const float*)d_in[18];
    const float* lfp_b  = (const float*)d_in[19];
    const float* ms_w1  = (const float*)d_in[20];
    const float* ms_b1  = (const float*)d_in[21];
    const float* ms_w2  = (const float*)d_in[22];
    const float* ms_g   = (const float*)d_in[23];
    const float* ms_b   = (const float*)d_in[24];
    const float* pp_g   = (const float*)d_in[25];
    const float* pp_b   = (const float*)d_in[26];
    const float* pp_w   = (const float*)d_in[27];
    float* out = (float*)d_out;

    float *f;
    uint32_t *y2;
    __half *wh;
    cudaGetSymbolAddress((void**)&f, g_f);
    cudaGetSymbolAddress((void**)&y2, g_y2);
    cudaGetSymbolAddress((void**)&wh, g_wh);

    const int SM96 = smem_bytes(96);   // 56320
    const int SM64 = smem_bytes(64);   // 51200
    cudaFuncSetAttribute(hmma_gemm<false, 96, 96, true>, cudaFuncAttributeMaxDynamicSharedMemorySize, SM96);
    cudaFuncSetAttribute(hmma_gemm<true, 64, 96, false>, cudaFuncAttributeMaxDynamicSharedMemorySize, SM64);
    cudaFuncSetAttribute(fused_mlp, cudaFuncAttributeMaxDynamicSharedMemorySize, FUSED_SMEM);

    // weight pre-conversion (transpose + fp16 round)
    conv_weights<<<(WTOTAL + 255) / 256, 256>>>(lfp_w, m0_w1, ms_w1, m0_w2, ms_w2, pp_w, ne_w3);

    // stage 1: neighbor embedding -> f [N,96]
    nbr_embed_kernel<<<NPTS / 8, 128>>>(
        x, xyz, knn, ne_w1, ne_g1, ne_b1, ne_w2, ne_g2, ne_b2,
        wh + WOFF_NE, nbr_g, nbr_b, f);

    auto launch_mlp = [&](int j) {
        fused_mlp<<<NPTS / 128, 256, FUSED_SMEM>>>(
            f,
            wh + WOFF_UP + (size_t)j * 36864,
            wh + WOFF_DOWN + (size_t)j * 36864,
            (j == 0) ? m0_b1 : (ms_b1 + (size_t)(j - 1) * HCH),
            (j == 0) ? m0_g  : (ms_g + (size_t)(j - 1) * DCH),
            (j == 0) ? m0_b  : (ms_b + (size_t)(j - 1) * DCH),
            f);
    };

    launch_mlp(0);
    for (int i = 0; i < 4; i++) {
        // y = f @ lfp_w[i]  (fp16 output)
        hmma_gemm<false, 96, 96, true><<<dim3(1, NPTS / 128), 256, SM96>>>(
            f, wh + WOFF_LFP + (size_t)i * 9216,
            y2, nullptr, nullptr, DCH);
        // f += bn(max_k y[knn] - y)  — flat indexed, NPTS*24 items
        lfp_edge_kernel<<<NPTS * 24 / 256, 256>>>(y2, knn, lfp_g + i * DCH, lfp_b + i * DCH, f);
        if (i & 1) launch_mlp(1 + i / 2);
    }

    // stage 4: out = bn(f) @ pp_w (BN folded into A load)
    hmma_gemm<true, 64, 96, false><<<dim3(HD / 64, NPTS / 128), 256, SM64>>>(
        f, wh + WOFF_HEAD,
        out, pp_g, pp_b, HD);
}